// round 10
// baseline (speedup 1.0000x reference)
#include <cuda_runtime.h>
#include <cuda_bf16.h>
#include <math.h>
#include <stdint.h>

#define BB    8
#define CIN   64
#define HH    128
#define WW    128
#define COUT  128
#define NPIX  (HH*WW)           // 16384
#define KTOT  (9*CIN)           // 576

// Scratch (__device__ globals; no allocation)
__device__ float g_x2 [BB*NPIX*CIN];          // NHWC fp32: [b][h][w][c]
__device__ __nv_bfloat16 g_xbhi[BB*NPIX*CIN]; // NHWC bf16 hi
__device__ __nv_bfloat16 g_xblo[BB*NPIX*CIN]; // NHWC bf16 lo
__device__ float g_offm[BB*NPIX*32];          // per-pixel [32]: 0..17 off, 18..26 mask
__device__ uint4 g_wfhi[9*8*4*32];            // k3 A frags (hi): [kk][mtile8][ks4][lane32]
__device__ uint4 g_wflo[9*8*4*32];            // k3 A frags (lo)
__device__ uint4 g_w2fhi[9*2*4*32];           // k2 A frags (hi): [kk][mtile2][ks4][lane32]
__device__ uint4 g_w2flo[9*2*4*32];           // k2 A frags (lo)

__device__ __forceinline__ uint32_t pack_bf16x2(float e0, float e1) {
    uint32_t r;
    asm("cvt.rn.bf16x2.f32 %0, %1, %2;" : "=r"(r) : "f"(e1), "f"(e0));
    return r;
}
__device__ __forceinline__ float bf16_hi(float v) {
    __nv_bfloat16 hb = __float2bfloat16(v);
    return __bfloat162float(hb);
}
__device__ __forceinline__ void mma_bf16(float* d, const uint32_t* a, uint32_t b0, uint32_t b1) {
    asm volatile(
        "mma.sync.aligned.m16n8k16.row.col.f32.bf16.bf16.f32 "
        "{%0,%1,%2,%3}, {%4,%5,%6,%7}, {%8,%9}, {%0,%1,%2,%3};"
        : "+f"(d[0]), "+f"(d[1]), "+f"(d[2]), "+f"(d[3])
        : "r"(a[0]), "r"(a[1]), "r"(a[2]), "r"(a[3]), "r"(b0), "r"(b1));
}
__device__ __forceinline__ uint32_t smem_u32(const void* p) {
    uint32_t a;
    asm("{ .reg .u64 t; cvta.to.shared.u64 t, %1; cvt.u32.u64 %0, t; }" : "=r"(a) : "l"(p));
    return a;
}
__device__ __forceinline__ void ldsm_x4(uint32_t& r0, uint32_t& r1, uint32_t& r2, uint32_t& r3,
                                        uint32_t addr) {
    asm volatile("ldmatrix.sync.aligned.m8n8.x4.shared.b16 {%0,%1,%2,%3}, [%4];"
                 : "=r"(r0), "=r"(r1), "=r"(r2), "=r"(r3) : "r"(addr));
}

// ---------------------------------------------------------------------------
// K0: weight prep — pre-packed mma A fragments (hi/lo) for k3 and k2.
// ---------------------------------------------------------------------------
__global__ void k0_wt(const float* __restrict__ rw,
                      const float* __restrict__ off_w,
                      const float* __restrict__ mod_w) {
    int i = blockIdx.x * 256 + threadIdx.x;
    if (i < 9 * 8 * 4 * 32) {
        int kk   = i >> 10;
        int rem  = i & 1023;
        int mt   = rem >> 7;
        int rem2 = rem & 127;
        int ks   = rem2 >> 5;
        int lane = rem2 & 31;
        int g = lane >> 2, t = lane & 3;
        int o0 = mt * 16 + g, o1 = o0 + 8;
        int c0 = ks * 16 + 2 * t, c1 = c0 + 8;

        float w00a = rw[(o0 * 64 + c0) * 9 + kk];
        float w00b = rw[(o0 * 64 + c0 + 1) * 9 + kk];
        float w10a = rw[(o1 * 64 + c0) * 9 + kk];
        float w10b = rw[(o1 * 64 + c0 + 1) * 9 + kk];
        float w01a = rw[(o0 * 64 + c1) * 9 + kk];
        float w01b = rw[(o0 * 64 + c1 + 1) * 9 + kk];
        float w11a = rw[(o1 * 64 + c1) * 9 + kk];
        float w11b = rw[(o1 * 64 + c1 + 1) * 9 + kk];

        float h00a = bf16_hi(w00a), h00b = bf16_hi(w00b);
        float h10a = bf16_hi(w10a), h10b = bf16_hi(w10b);
        float h01a = bf16_hi(w01a), h01b = bf16_hi(w01b);
        float h11a = bf16_hi(w11a), h11b = bf16_hi(w11b);

        uint4 hi, lo;
        hi.x = pack_bf16x2(h00a, h00b);
        hi.y = pack_bf16x2(h10a, h10b);
        hi.z = pack_bf16x2(h01a, h01b);
        hi.w = pack_bf16x2(h11a, h11b);
        lo.x = pack_bf16x2(w00a - h00a, w00b - h00b);
        lo.y = pack_bf16x2(w10a - h10a, w10b - h10b);
        lo.z = pack_bf16x2(w01a - h01a, w01b - h01b);
        lo.w = pack_bf16x2(w11a - h11a, w11b - h11b);
        g_wfhi[i] = hi;
        g_wflo[i] = lo;
    }
    if (i < 9 * 2 * 4 * 32) {
        int lane = i & 31;
        int ks = (i >> 5) & 3;
        int mt = (i >> 7) & 1;
        int kk = i >> 8;
        int g = lane >> 2, t = lane & 3;
        int o0 = mt * 16 + g, o1 = o0 + 8;
        int c0 = ks * 16 + 2 * t, c1 = c0 + 8;

        auto w2v = [&](int o, int c) -> float {
            if (o < 18)      return off_w[(o * 64 + c) * 9 + kk];
            else if (o < 27) return mod_w[((o - 18) * 64 + c) * 9 + kk];
            return 0.f;
        };
        float w00a = w2v(o0, c0), w00b = w2v(o0, c0 + 1);
        float w10a = w2v(o1, c0), w10b = w2v(o1, c0 + 1);
        float w01a = w2v(o0, c1), w01b = w2v(o0, c1 + 1);
        float w11a = w2v(o1, c1), w11b = w2v(o1, c1 + 1);

        float h00a = bf16_hi(w00a), h00b = bf16_hi(w00b);
        float h10a = bf16_hi(w10a), h10b = bf16_hi(w10b);
        float h01a = bf16_hi(w01a), h01b = bf16_hi(w01b);
        float h11a = bf16_hi(w11a), h11b = bf16_hi(w11b);

        uint4 hi, lo;
        hi.x = pack_bf16x2(h00a, h00b);
        hi.y = pack_bf16x2(h10a, h10b);
        hi.z = pack_bf16x2(h01a, h01b);
        hi.w = pack_bf16x2(h11a, h11b);
        lo.x = pack_bf16x2(w00a - h00a, w00b - h00b);
        lo.y = pack_bf16x2(w10a - h10a, w10b - h10b);
        lo.z = pack_bf16x2(w01a - h01a, w01b - h01b);
        lo.w = pack_bf16x2(w11a - h11a, w11b - h11b);
        g_w2fhi[i] = hi;
        g_w2flo[i] = lo;
    }
}

// ---------------------------------------------------------------------------
// K1: 1x1 pre-conv, NCHW in -> NHWC fp32 (g_x2) + NHWC bf16 hi/lo
// ---------------------------------------------------------------------------
__global__ void __launch_bounds__(128) k1_pre(const float* __restrict__ x,
                                              const float* __restrict__ pre_w,
                                              const float* __restrict__ pre_b) {
    __shared__ float wsm[64 * 64];
    __shared__ float bsm[64];
    int tid = threadIdx.x;
    for (int i = tid; i < 4096; i += 128) {
        int co = i & 63, ci = i >> 6;
        wsm[ci * 64 + co] = pre_w[co * 64 + ci];
    }
    if (tid < 64) bsm[tid] = pre_b[tid];
    __syncthreads();

    int bh = blockIdx.x;
    int b = bh >> 7, h = bh & 127;
    int w = tid;

    const float* xp = x + (size_t)b * 64 * NPIX + h * WW + w;
    float xin[64];
#pragma unroll
    for (int ci = 0; ci < 64; ci++) xin[ci] = xp[(size_t)ci * NPIX];

    size_t pbase = ((size_t)bh * WW + w) * 64;
    float4* out4 = (float4*)(g_x2 + pbase);
    const float4* wsm4 = (const float4*)wsm;
    const float4* b4 = (const float4*)bsm;
#pragma unroll
    for (int cog = 0; cog < 16; cog++) {
        float4 acc = b4[cog];
#pragma unroll
        for (int ci = 0; ci < 64; ci++) {
            float4 wv = wsm4[ci * 16 + cog];
            acc.x += xin[ci] * wv.x;
            acc.y += xin[ci] * wv.y;
            acc.z += xin[ci] * wv.z;
            acc.w += xin[ci] * wv.w;
        }
        out4[cog] = acc;
        float h0 = bf16_hi(acc.x), h1 = bf16_hi(acc.y);
        float h2 = bf16_hi(acc.z), h3 = bf16_hi(acc.w);
        uint2 vh = make_uint2(pack_bf16x2(h0, h1), pack_bf16x2(h2, h3));
        uint2 vl = make_uint2(pack_bf16x2(acc.x - h0, acc.y - h1),
                              pack_bf16x2(acc.z - h2, acc.w - h3));
        *(uint2*)(g_xbhi + pbase + cog * 4) = vh;
        *(uint2*)(g_xblo + pbase + cog * 4) = vl;
    }
}

// ---------------------------------------------------------------------------
// K2: offset+mask 3x3 conv via HMMA hi/lo 3-pass + ldmatrix B-frags.
// ---------------------------------------------------------------------------
extern __shared__ float dyn_smem[];
#define S_STRIDE  144   // bytes per px row (72 bf16)

__global__ void __launch_bounds__(256) k2_offmask(const float* __restrict__ off_b,
                                                  const float* __restrict__ mod_b) {
    char* smp = (char*)dyn_smem;
    char* s_hi = smp;
    char* s_lo = smp + 18432;

    int tid = threadIdx.x;
    int warp = tid >> 5, lane = tid & 31;
    int g = lane >> 2, t = lane & 3;
    int bx = blockIdx.x;
    int b = bx >> 7, h = bx & 127;
    size_t pixbase = (size_t)bx * 128;

    int warp_m = warp >> 2;     // 0..1
    int warp_n = warp & 3;      // 0..3

    int pair = lane >> 3, rr = lane & 7;
    uint32_t su32 = smem_u32(smp);
    uint32_t rowpart = (uint32_t)((warp_n * 32 + ((pair >> 1) << 3) + rr) * S_STRIDE
                                  + (pair & 1) * 16);

    float acc[4][4];
#pragma unroll
    for (int nt = 0; nt < 4; nt++)
#pragma unroll
        for (int j = 0; j < 4; j++) acc[nt][j] = 0.f;

    for (int kk = 0; kk < 9; kk++) {
        int ky = kk / 3, kx = kk - ky * 3;
        __syncthreads();
        int y = h - 1 + ky;
        bool yok = (unsigned)y < 128u;
        const __nv_bfloat16* rh = g_xbhi + ((size_t)(b * 128 + (yok ? y : 0)) * 128) * 64;
        const __nv_bfloat16* rl = g_xblo + ((size_t)(b * 128 + (yok ? y : 0)) * 128) * 64;
        for (int i = tid; i < 2048; i += 256) {
            int px = i >> 4, c4 = i & 15;
            int xg = px - 1 + kx;
            uint2 vh = make_uint2(0u, 0u), vl = make_uint2(0u, 0u);
            if (yok && (unsigned)xg < 128u) {
                vh = *(const uint2*)(rh + xg * 64 + c4 * 4);
                vl = *(const uint2*)(rl + xg * 64 + c4 * 4);
            }
            *(uint2*)(s_hi + px * S_STRIDE + c4 * 8) = vh;
            *(uint2*)(s_lo + px * S_STRIDE + c4 * 8) = vl;
        }
        __syncthreads();

        const uint4* wfh = g_w2fhi + (kk * 2 + warp_m) * 4 * 32;
        const uint4* wfl = g_w2flo + (kk * 2 + warp_m) * 4 * 32;
#pragma unroll
        for (int ks = 0; ks < 4; ks++) {
            uint4 ah = __ldg(&wfh[ks * 32 + lane]);
            uint4 al = __ldg(&wfl[ks * 32 + lane]);
            uint32_t bh0[4], bh1[4], bl0[4], bl1[4];
            uint32_t hb = su32 + rowpart + ks * 32;
            ldsm_x4(bh0[0], bh1[0], bh0[1], bh1[1], hb);
            ldsm_x4(bh0[2], bh1[2], bh0[3], bh1[3], hb + 16 * S_STRIDE);
            ldsm_x4(bl0[0], bl1[0], bl0[1], bl1[1], hb + 18432);
            ldsm_x4(bl0[2], bl1[2], bl0[3], bl1[3], hb + 18432 + 16 * S_STRIDE);
#pragma unroll
            for (int nt = 0; nt < 4; nt++) {
                mma_bf16(acc[nt], (const uint32_t*)&ah, bh0[nt], bh1[nt]);
                mma_bf16(acc[nt], (const uint32_t*)&ah, bl0[nt], bl1[nt]);
                mma_bf16(acc[nt], (const uint32_t*)&al, bh0[nt], bh1[nt]);
            }
        }
    }

    int o0 = warp_m * 16 + g, o1 = o0 + 8;
    auto wr = [&](int o, int px, float v) {
        if (o >= 27) return;
        v += (o < 18) ? __ldg(off_b + o) : __ldg(mod_b + o - 18);
        if (o >= 18) v = 2.0f / (1.0f + expf(-v));
        g_offm[(pixbase + px) * 32 + o] = v;
    };
#pragma unroll
    for (int nt = 0; nt < 4; nt++) {
        int px = warp_n * 32 + nt * 8 + 2 * t;
        wr(o0, px,     acc[nt][0]);
        wr(o0, px + 1, acc[nt][1]);
        wr(o1, px,     acc[nt][2]);
        wr(o1, px + 1, acc[nt][3]);
    }
}
#define K2_SMEM_BYTES 36864

// ---------------------------------------------------------------------------
// K3: deformable sampling + HMMA hi/lo 3-pass, software-pipelined +
// smem-staged A fragments (bulk copy per kk, LDS instead of scattered LDG)
// + kk-stagger across CTAs. 256 threads / 8 warps, 2 CTAs/SM.
// smem: s_hi[2],s_lo[2] 0..36864 | OSM 36864 | IBUF 45312 | WBUF 54528
//       WFRAG 63744 (hi 16KB + lo 16KB) -> total 96512 B
// ---------------------------------------------------------------------------
#define OSM_OFF   36864
#define IBUF_OFF  45312
#define WBUF_OFF  54528
#define WFRAG_OFF 63744
#define K3_SMEM_BYTES 96512

__global__ void __launch_bounds__(256, 2) k3_main(float* __restrict__ out) {
    char* smp = (char*)dyn_smem;

    int tid = threadIdx.x;
    int warp = tid >> 5, lane = tid & 31;
    int g = lane >> 2, t = lane & 3;
    int bx = blockIdx.x;
    int b = bx >> 8;
    int h = (bx >> 1) & 127;
    int seg = bx & 1;
    int w0 = seg * 64;
    size_t pixbase = (((size_t)(b * 128 + h)) * 128 + w0);

    float* osm = (float*)(smp + OSM_OFF);
    int4* ibuf = (int4*)(smp + IBUF_OFF);
    float4* wbuf = (float4*)(smp + WBUF_OFF);

    for (int i = tid; i < 2048; i += 256) {
        int px = i >> 5, j = i & 31;
        osm[px * 33 + j] = g_offm[(pixbase + px) * 32 + j];
    }
    __syncthreads();

    for (int i = tid; i < 9 * 64; i += 256) {
        int kk = i >> 6, px = i & 63;
        int ky = kk / 3, kx = kk - ky * 3;
        float dy = osm[px * 33 + 2 * kk];
        float dx = osm[px * 33 + 2 * kk + 1];
        float m  = osm[px * 33 + 18 + kk];
        float py  = (float)(h - 1 + ky) + dy;
        float pxf = (float)(w0 + px - 1 + kx) + dx;
        float y0f = floorf(py), x0f = floorf(pxf);
        float wy = py - y0f, wx = pxf - x0f;
        int y0 = (int)y0f, x0 = (int)x0f;
        int y1 = y0 + 1, x1 = x0 + 1;
        float w00 = (1.f - wy) * (1.f - wx) * m;
        float w01 = (1.f - wy) * wx * m;
        float w10 = wy * (1.f - wx) * m;
        float w11 = wy * wx * m;
        if ((unsigned)y0 >= 128u) { w00 = 0.f; w01 = 0.f; }
        if ((unsigned)y1 >= 128u) { w10 = 0.f; w11 = 0.f; }
        if ((unsigned)x0 >= 128u) { w00 = 0.f; w10 = 0.f; }
        if ((unsigned)x1 >= 128u) { w01 = 0.f; w11 = 0.f; }
        int yc0 = min(max(y0, 0), 127), yc1 = min(max(y1, 0), 127);
        int xc0 = min(max(x0, 0), 127), xc1 = min(max(x1, 0), 127);
        ibuf[i] = make_int4((yc0 * 128 + xc0) * 64, (yc0 * 128 + xc1) * 64,
                            (yc1 * 128 + xc0) * 64, (yc1 * 128 + xc1) * 64);
        wbuf[i] = make_float4(w00, w01, w10, w11);
    }
    __syncthreads();

    const float* bbase = g_x2 + (size_t)b * NPIX * 64;
    int pxs = lane >> 3;
    int c8  = lane & 7;

    int warp_m = warp >> 1;
    int warp_n = warp & 1;

    int pair = lane >> 3, rr = lane & 7;
    uint32_t su32 = smem_u32(smp);
    uint32_t rowpart = (uint32_t)((warp_n * 32 + ((pair >> 1) << 3) + rr) * S_STRIDE
                                  + (pair & 1) * 16);

    const uint4* wsm_hi = (const uint4*)(smp + WFRAG_OFF);
    const uint4* wsm_lo = (const uint4*)(smp + WFRAG_OFF + 16384);

    float acc[2][4][4];
#pragma unroll
    for (int mt = 0; mt < 2; mt++)
#pragma unroll
        for (int nt = 0; nt < 4; nt++)
#pragma unroll
            for (int j = 0; j < 4; j++) acc[mt][nt][j] = 0.f;

    auto prefetch = [&](const int4* ib, const float4* wb, int it,
                        float4* r, float4& wtv, uint32_t& by) {
        int half = it & 1;
        int px = (it >> 1) * 4 + pxs;
        int4 off = ib[px];
        wtv = wb[px];
        int c4 = half * 8 + c8;
        r[0] = ((const float4*)(bbase + off.x))[c4];
        r[1] = ((const float4*)(bbase + off.y))[c4];
        r[2] = ((const float4*)(bbase + off.z))[c4];
        r[3] = ((const float4*)(bbase + off.w))[c4];
        by = (uint32_t)(px * S_STRIDE + c4 * 8);
    };
    auto cvst = [&](const float4* r, float4 wtv, uint32_t by, char* dh, char* dl) {
        float v0 = wtv.x * r[0].x + wtv.y * r[1].x + wtv.z * r[2].x + wtv.w * r[3].x;
        float v1 = wtv.x * r[0].y + wtv.y * r[1].y + wtv.z * r[2].y + wtv.w * r[3].y;
        float v2 = wtv.x * r[0].z + wtv.y * r[1].z + wtv.z * r[2].z + wtv.w * r[3].z;
        float v3 = wtv.x * r[0].w + wtv.y * r[1].w + wtv.z * r[2].w + wtv.w * r[3].w;
        float h0 = bf16_hi(v0), h1 = bf16_hi(v1);
        float h2 = bf16_hi(v2), h3 = bf16_hi(v3);
        *(uint2*)(dh + by) = make_uint2(pack_bf16x2(h0, h1), pack_bf16x2(h2, h3));
        *(uint2*)(dl + by) = make_uint2(pack_bf16x2(v0 - h0, v1 - h1),
                                        pack_bf16x2(v2 - h2, v3 - h3));
    };

    // stagger start phase across CTA parity (accumulation order irrelevant)
    int start = (bx & 1) * 4;

    // prologue: fill s[0] with kk=start samples
    {
        float4 r[4]; float4 wtv; uint32_t by;
        for (int it = warp; it < 32; it += 8) {
            prefetch(ibuf + start * 64, wbuf + start * 64, it, r, wtv, by);
            cvst(r, wtv, by, smp, smp + 18432);
        }
    }
    __syncthreads();

    for (int i = 0; i < 9; i++) {
        int kk = start + i; if (kk >= 9) kk -= 9;
        int knext = kk + 1; if (knext >= 9) knext -= 9;
        int p = i & 1;
        char* nh = smp + (p ^ 1) * 9216;
        char* nl = smp + 18432 + (p ^ 1) * 9216;
        const int4* ib1 = ibuf + knext * 64;
        const float4* wb1 = wbuf + knext * 64;
        bool pf = (i < 8);
        uint32_t sbh = su32 + p * 9216 + rowpart;

        // cooperative bulk copy of this kk's A fragments into smem
        {
            const uint4* sh_ = g_wfhi + kk * 1024;
            const uint4* sl_ = g_wflo + kk * 1024;
            uint4* dh_ = (uint4*)(smp + WFRAG_OFF);
            uint4* dl_ = (uint4*)(smp + WFRAG_OFF + 16384);
            for (int j = tid; j < 1024; j += 256) {
                dh_[j] = __ldg(&sh_[j]);
                dl_[j] = __ldg(&sl_[j]);
            }
        }

        float4 ra[2][4]; float4 rw_[2]; uint32_t rby[2];
        if (pf) {
            prefetch(ib1, wb1, warp,     ra[0], rw_[0], rby[0]);
            prefetch(ib1, wb1, warp + 8, ra[1], rw_[1], rby[1]);
        }
        __syncthreads();   // A frags visible

        auto do_mma2 = [&](int ks0) {
#pragma unroll
            for (int ks = ks0; ks < ks0 + 2; ks++) {
                uint4 ah0 = wsm_hi[((warp_m * 2 + 0) * 4 + ks) * 32 + lane];
                uint4 ah1 = wsm_hi[((warp_m * 2 + 1) * 4 + ks) * 32 + lane];
                uint32_t bh0[4], bh1[4], bl0[4], bl1[4];
                uint32_t hb = sbh + ks * 32;
                ldsm_x4(bh0[0], bh1[0], bh0[1], bh1[1], hb);
                ldsm_x4(bh0[2], bh1[2], bh0[3], bh1[3], hb + 16 * S_STRIDE);
                ldsm_x4(bl0[0], bl1[0], bl0[1], bl1[1], hb + 18432);
                ldsm_x4(bl0[2], bl1[2], bl0[3], bl1[3], hb + 18432 + 16 * S_STRIDE);
#pragma unroll
                for (int nt = 0; nt < 4; nt++) {
                    mma_bf16(acc[0][nt], (const uint32_t*)&ah0, bh0[nt], bh1[nt]);
                    mma_bf16(acc[1][nt], (const uint32_t*)&ah1, bh0[nt], bh1[nt]);
                    mma_bf16(acc[0][nt], (const uint32_t*)&ah0, bl0[nt], bl1[nt]);
                    mma_bf16(acc[1][nt], (const uint32_t*)&ah1, bl0[nt], bl1[nt]);
                }
                uint4 al0 = wsm_lo[((warp_m * 2 + 0) * 4 + ks) * 32 + lane];
                uint4 al1 = wsm_lo[((warp_m * 2 + 1) * 4 + ks) * 32 + lane];
#pragma unroll
                for (int nt = 0; nt < 4; nt++) {
                    mma_bf16(acc[0][nt], (const uint32_t*)&al0, bh0[nt], bh1[nt]);
                    mma_bf16(acc[1][nt], (const uint32_t*)&al1, bh0[nt], bh1[nt]);
                }
            }
        };

        do_mma2(0);

        if (pf) {
            cvst(ra[0], rw_[0], rby[0], nh, nl);
            cvst(ra[1], rw_[1], rby[1], nh, nl);
            prefetch(ib1, wb1, warp + 16, ra[0], rw_[0], rby[0]);
            prefetch(ib1, wb1, warp + 24, ra[1], rw_[1], rby[1]);
        }

        do_mma2(2);

        if (pf) {
            cvst(ra[0], rw_[0], rby[0], nh, nl);
            cvst(ra[1], rw_[1], rby[1], nh, nl);
        }
        __syncthreads();
    }

    // epilogue: direct STG from C fragments
    float* ob = out + ((size_t)b * COUT) * NPIX + h * WW + w0;
#pragma unroll
    for (int mt = 0; mt < 2; mt++) {
        int o = warp_m * 32 + mt * 16 + g;
#pragma unroll
        for (int nt = 0; nt < 4; nt++) {
            int px = warp_n * 32 + nt * 8 + 2 * t;
            float* p0 = ob + (size_t)o * NPIX + px;
            *(float2*)p0 = make_float2(acc[mt][nt][0], acc[mt][nt][1]);
            float* p1 = p0 + 8 * (size_t)NPIX;
            *(float2*)p1 = make_float2(acc[mt][nt][2], acc[mt][nt][3]);
        }
    }
}

// ---------------------------------------------------------------------------
extern "C" void kernel_launch(void* const* d_in, const int* in_sizes, int n_in,
                              void* d_out, int out_size) {
    const float* x     = (const float*)d_in[0];
    const float* pre_w = (const float*)d_in[1];
    const float* pre_b = (const float*)d_in[2];
    const float* off_w = (const float*)d_in[3];
    const float* off_b = (const float*)d_in[4];
    const float* mod_w = (const float*)d_in[5];
    const float* mod_b = (const float*)d_in[6];
    const float* reg_w = (const float*)d_in[7];
    float* out = (float*)d_out;

    cudaFuncSetAttribute(k2_offmask, cudaFuncAttributeMaxDynamicSharedMemorySize, K2_SMEM_BYTES);
    cudaFuncSetAttribute(k3_main, cudaFuncAttributeMaxDynamicSharedMemorySize, K3_SMEM_BYTES);

    k0_wt<<<36, 256>>>(reg_w, off_w, mod_w);
    k1_pre<<<BB * HH, 128>>>(x, pre_w, pre_b);
    k2_offmask<<<BB * HH, 256, K2_SMEM_BYTES>>>(off_b, mod_b);
    k3_main<<<BB * HH * 2, 256, K3_SMEM_BYTES>>>(out);
}

// round 11
// speedup vs baseline: 1.7288x; 1.7288x over previous
#include <cuda_runtime.h>
#include <cuda_fp16.h>
#include <math.h>
#include <stdint.h>

#define BB    8
#define CIN   64
#define HH    128
#define WW    128
#define COUT  128
#define NPIX  (HH*WW)           // 16384
#define KTOT  (9*CIN)           // 576

// Scratch (__device__ globals; no allocation)
__device__ __half g_x2h[BB*NPIX*CIN];         // NHWC fp16: [b][h][w][c]
__device__ float g_offm[BB*NPIX*32];          // per-pixel [32]: 0..17 off, 18..26 mask
__device__ uint4 g_wf [9*8*4*32];             // k3 A frags fp16: [kk][mtile8][ks4][lane32]
__device__ uint4 g_w2f[9*2*4*32];             // k2 A frags fp16: [kk][mtile2][ks4][lane32]

__device__ __forceinline__ uint32_t pack_f16x2(float e0, float e1) {
    __half2 h = __floats2half2_rn(e0, e1);    // x=e0 (low), y=e1 (high)
    return *(uint32_t*)&h;
}
__device__ __forceinline__ void mma_f16(float* d, const uint32_t* a, uint32_t b0, uint32_t b1) {
    asm volatile(
        "mma.sync.aligned.m16n8k16.row.col.f32.f16.f16.f32 "
        "{%0,%1,%2,%3}, {%4,%5,%6,%7}, {%8,%9}, {%0,%1,%2,%3};"
        : "+f"(d[0]), "+f"(d[1]), "+f"(d[2]), "+f"(d[3])
        : "r"(a[0]), "r"(a[1]), "r"(a[2]), "r"(a[3]), "r"(b0), "r"(b1));
}
__device__ __forceinline__ uint32_t smem_u32(const void* p) {
    uint32_t a;
    asm("{ .reg .u64 t; cvta.to.shared.u64 t, %1; cvt.u32.u64 %0, t; }" : "=r"(a) : "l"(p));
    return a;
}
__device__ __forceinline__ void ldsm_x4(uint32_t& r0, uint32_t& r1, uint32_t& r2, uint32_t& r3,
                                        uint32_t addr) {
    asm volatile("ldmatrix.sync.aligned.m8n8.x4.shared.b16 {%0,%1,%2,%3}, [%4];"
                 : "=r"(r0), "=r"(r1), "=r"(r2), "=r"(r3) : "r"(addr));
}

// ---------------------------------------------------------------------------
// K0: weight prep — fp16 mma A fragments for k3 and k2.
// ---------------------------------------------------------------------------
__global__ void k0_wt(const float* __restrict__ rw,
                      const float* __restrict__ off_w,
                      const float* __restrict__ mod_w) {
    int i = blockIdx.x * 256 + threadIdx.x;
    if (i < 9 * 8 * 4 * 32) {
        int kk   = i >> 10;
        int rem  = i & 1023;
        int mt   = rem >> 7;
        int rem2 = rem & 127;
        int ks   = rem2 >> 5;
        int lane = rem2 & 31;
        int g = lane >> 2, t = lane & 3;
        int o0 = mt * 16 + g, o1 = o0 + 8;
        int c0 = ks * 16 + 2 * t, c1 = c0 + 8;

        uint4 f;
        f.x = pack_f16x2(rw[(o0 * 64 + c0) * 9 + kk], rw[(o0 * 64 + c0 + 1) * 9 + kk]);
        f.y = pack_f16x2(rw[(o1 * 64 + c0) * 9 + kk], rw[(o1 * 64 + c0 + 1) * 9 + kk]);
        f.z = pack_f16x2(rw[(o0 * 64 + c1) * 9 + kk], rw[(o0 * 64 + c1 + 1) * 9 + kk]);
        f.w = pack_f16x2(rw[(o1 * 64 + c1) * 9 + kk], rw[(o1 * 64 + c1 + 1) * 9 + kk]);
        g_wf[i] = f;
    }
    if (i < 9 * 2 * 4 * 32) {
        int lane = i & 31;
        int ks = (i >> 5) & 3;
        int mt = (i >> 7) & 1;
        int kk = i >> 8;
        int g = lane >> 2, t = lane & 3;
        int o0 = mt * 16 + g, o1 = o0 + 8;
        int c0 = ks * 16 + 2 * t, c1 = c0 + 8;

        auto w2v = [&](int o, int c) -> float {
            if (o < 18)      return off_w[(o * 64 + c) * 9 + kk];
            else if (o < 27) return mod_w[((o - 18) * 64 + c) * 9 + kk];
            return 0.f;
        };
        uint4 f;
        f.x = pack_f16x2(w2v(o0, c0), w2v(o0, c0 + 1));
        f.y = pack_f16x2(w2v(o1, c0), w2v(o1, c0 + 1));
        f.z = pack_f16x2(w2v(o0, c1), w2v(o0, c1 + 1));
        f.w = pack_f16x2(w2v(o1, c1), w2v(o1, c1 + 1));
        g_w2f[i] = f;
    }
}

// ---------------------------------------------------------------------------
// K1: 1x1 pre-conv, NCHW in -> NHWC fp16 (g_x2h)
// ---------------------------------------------------------------------------
__global__ void __launch_bounds__(128) k1_pre(const float* __restrict__ x,
                                              const float* __restrict__ pre_w,
                                              const float* __restrict__ pre_b) {
    __shared__ float wsm[64 * 64];
    __shared__ float bsm[64];
    int tid = threadIdx.x;
    for (int i = tid; i < 4096; i += 128) {
        int co = i & 63, ci = i >> 6;
        wsm[ci * 64 + co] = pre_w[co * 64 + ci];
    }
    if (tid < 64) bsm[tid] = pre_b[tid];
    __syncthreads();

    int bh = blockIdx.x;
    int b = bh >> 7, h = bh & 127;
    int w = tid;

    const float* xp = x + (size_t)b * 64 * NPIX + h * WW + w;
    float xin[64];
#pragma unroll
    for (int ci = 0; ci < 64; ci++) xin[ci] = xp[(size_t)ci * NPIX];

    size_t pbase = ((size_t)bh * WW + w) * 64;
    const float4* wsm4 = (const float4*)wsm;
    const float4* b4 = (const float4*)bsm;
#pragma unroll
    for (int cog = 0; cog < 16; cog++) {
        float4 acc = b4[cog];
#pragma unroll
        for (int ci = 0; ci < 64; ci++) {
            float4 wv = wsm4[ci * 16 + cog];
            acc.x += xin[ci] * wv.x;
            acc.y += xin[ci] * wv.y;
            acc.z += xin[ci] * wv.z;
            acc.w += xin[ci] * wv.w;
        }
        uint2 v = make_uint2(pack_f16x2(acc.x, acc.y), pack_f16x2(acc.z, acc.w));
        *(uint2*)(g_x2h + pbase + cog * 4) = v;
    }
}

// ---------------------------------------------------------------------------
// K2: offset+mask 3x3 conv via single-pass fp16 HMMA + ldmatrix B-frags.
// Block = one row (128 px), 256 threads / 8 warps. M=32(co pad), N=128, K=576.
// smem: s [128px][72 fp16] stride 144B = 18432 B
// ---------------------------------------------------------------------------
extern __shared__ float dyn_smem[];
#define S_STRIDE  144   // bytes per px row (64 fp16 data + pad)

__global__ void __launch_bounds__(256) k2_offmask(const float* __restrict__ off_b,
                                                  const float* __restrict__ mod_b) {
    char* smp = (char*)dyn_smem;

    int tid = threadIdx.x;
    int warp = tid >> 5, lane = tid & 31;
    int g = lane >> 2, t = lane & 3;
    int bx = blockIdx.x;
    int b = bx >> 7, h = bx & 127;
    size_t pixbase = (size_t)bx * 128;

    int warp_m = warp >> 2;     // 0..1
    int warp_n = warp & 3;      // 0..3

    int pair = lane >> 3, rr = lane & 7;
    uint32_t su32 = smem_u32(smp);
    uint32_t rowpart = (uint32_t)((warp_n * 32 + ((pair >> 1) << 3) + rr) * S_STRIDE
                                  + (pair & 1) * 16);

    float acc[4][4];
#pragma unroll
    for (int nt = 0; nt < 4; nt++)
#pragma unroll
        for (int j = 0; j < 4; j++) acc[nt][j] = 0.f;

    for (int kk = 0; kk < 9; kk++) {
        int ky = kk / 3, kx = kk - ky * 3;
        __syncthreads();
        int y = h - 1 + ky;
        bool yok = (unsigned)y < 128u;
        const __half* row = g_x2h + ((size_t)(b * 128 + (yok ? y : 0)) * 128) * 64;
        for (int i = tid; i < 1024; i += 256) {
            int px = i >> 3, cg = i & 7;      // cg: uint4 (8 fp16) group
            int xg = px - 1 + kx;
            uint4 v = make_uint4(0u, 0u, 0u, 0u);
            if (yok && (unsigned)xg < 128u)
                v = *(const uint4*)(row + xg * 64 + cg * 8);
            *(uint4*)(smp + px * S_STRIDE + cg * 16) = v;
        }
        __syncthreads();

        const uint4* wfh = g_w2f + (kk * 2 + warp_m) * 4 * 32;
#pragma unroll
        for (int ks = 0; ks < 4; ks++) {
            uint4 ah = __ldg(&wfh[ks * 32 + lane]);
            uint32_t b0[4], b1[4];
            uint32_t hb = su32 + rowpart + ks * 32;
            ldsm_x4(b0[0], b1[0], b0[1], b1[1], hb);
            ldsm_x4(b0[2], b1[2], b0[3], b1[3], hb + 16 * S_STRIDE);
#pragma unroll
            for (int nt = 0; nt < 4; nt++)
                mma_f16(acc[nt], (const uint32_t*)&ah, b0[nt], b1[nt]);
        }
    }

    int o0 = warp_m * 16 + g, o1 = o0 + 8;
    auto wr = [&](int o, int px, float v) {
        if (o >= 27) return;
        v += (o < 18) ? __ldg(off_b + o) : __ldg(mod_b + o - 18);
        if (o >= 18) v = 2.0f / (1.0f + expf(-v));
        g_offm[(pixbase + px) * 32 + o] = v;
    };
#pragma unroll
    for (int nt = 0; nt < 4; nt++) {
        int px = warp_n * 32 + nt * 8 + 2 * t;
        wr(o0, px,     acc[nt][0]);
        wr(o0, px + 1, acc[nt][1]);
        wr(o1, px,     acc[nt][2]);
        wr(o1, px + 1, acc[nt][3]);
    }
}
#define K2_SMEM_BYTES 18432

// ---------------------------------------------------------------------------
// K3: deformable sampling (fp16 gathers) + single-pass fp16 HMMA, pipelined.
// Block = half row (64 px), 256 threads / 8 warps, 2 CTAs/SM.
// smem: s[2] 0..18432 (2 x 9216) | OSM 18432 (8448) | IBUF 26880 (9216) |
//       WBUF 36096 (9216) -> total 45312 B
// ---------------------------------------------------------------------------
#define OSM_OFF   18432
#define IBUF_OFF  26880
#define WBUF_OFF  36096
#define K3_SMEM_BYTES 45312

__global__ void __launch_bounds__(256, 2) k3_main(float* __restrict__ out) {
    char* smp = (char*)dyn_smem;

    int tid = threadIdx.x;
    int warp = tid >> 5, lane = tid & 31;
    int g = lane >> 2, t = lane & 3;
    int bx = blockIdx.x;
    int b = bx >> 8;
    int h = (bx >> 1) & 127;
    int seg = bx & 1;
    int w0 = seg * 64;
    size_t pixbase = (((size_t)(b * 128 + h)) * 128 + w0);

    float* osm = (float*)(smp + OSM_OFF);
    int4* ibuf = (int4*)(smp + IBUF_OFF);
    float4* wbuf = (float4*)(smp + WBUF_OFF);

    for (int i = tid; i < 2048; i += 256) {
        int px = i >> 5, j = i & 31;
        osm[px * 33 + j] = g_offm[(pixbase + px) * 32 + j];
    }
    __syncthreads();

    for (int i = tid; i < 9 * 64; i += 256) {
        int kk = i >> 6, px = i & 63;
        int ky = kk / 3, kx = kk - ky * 3;
        float dy = osm[px * 33 + 2 * kk];
        float dx = osm[px * 33 + 2 * kk + 1];
        float m  = osm[px * 33 + 18 + kk];
        float py  = (float)(h - 1 + ky) + dy;
        float pxf = (float)(w0 + px - 1 + kx) + dx;
        float y0f = floorf(py), x0f = floorf(pxf);
        float wy = py - y0f, wx = pxf - x0f;
        int y0 = (int)y0f, x0 = (int)x0f;
        int y1 = y0 + 1, x1 = x0 + 1;
        float w00 = (1.f - wy) * (1.f - wx) * m;
        float w01 = (1.f - wy) * wx * m;
        float w10 = wy * (1.f - wx) * m;
        float w11 = wy * wx * m;
        if ((unsigned)y0 >= 128u) { w00 = 0.f; w01 = 0.f; }
        if ((unsigned)y1 >= 128u) { w10 = 0.f; w11 = 0.f; }
        if ((unsigned)x0 >= 128u) { w00 = 0.f; w10 = 0.f; }
        if ((unsigned)x1 >= 128u) { w01 = 0.f; w11 = 0.f; }
        int yc0 = min(max(y0, 0), 127), yc1 = min(max(y1, 0), 127);
        int xc0 = min(max(x0, 0), 127), xc1 = min(max(x1, 0), 127);
        ibuf[i] = make_int4((yc0 * 128 + xc0) * 64, (yc0 * 128 + xc1) * 64,
                            (yc1 * 128 + xc0) * 64, (yc1 * 128 + xc1) * 64);
        wbuf[i] = make_float4(w00, w01, w10, w11);
    }
    __syncthreads();

    const __half* bbase = g_x2h + (size_t)b * NPIX * 64;
    int pxs = lane >> 3;     // 0..3
    int c8  = lane & 7;      // 0..7 -> uint4 group within 64-ch pixel

    int warp_m = warp >> 1;
    int warp_n = warp & 1;

    int pair = lane >> 3, rr = lane & 7;
    uint32_t su32 = smem_u32(smp);
    uint32_t rowpart = (uint32_t)((warp_n * 32 + ((pair >> 1) << 3) + rr) * S_STRIDE
                                  + (pair & 1) * 16);

    float acc[2][4][4];
#pragma unroll
    for (int mt = 0; mt < 2; mt++)
#pragma unroll
        for (int nt = 0; nt < 4; nt++)
#pragma unroll
            for (int j = 0; j < 4; j++) acc[mt][nt][j] = 0.f;

    // gather: 16 groups of 4 px per kk; each lane covers 8 channels of 1 px
    auto prefetch = [&](const int4* ib, const float4* wb, int it,
                        uint4* r, float4& wtv, uint32_t& by) {
        int px = it * 4 + pxs;
        int4 off = ib[px];
        wtv = wb[px];
        r[0] = *(const uint4*)(bbase + off.x + c8 * 8);
        r[1] = *(const uint4*)(bbase + off.y + c8 * 8);
        r[2] = *(const uint4*)(bbase + off.z + c8 * 8);
        r[3] = *(const uint4*)(bbase + off.w + c8 * 8);
        by = (uint32_t)(px * S_STRIDE + c8 * 16);
    };
    auto cvst = [&](const uint4* r, float4 wtv, uint32_t by, char* dst) {
        const uint32_t* ra = (const uint32_t*)&r[0];
        const uint32_t* rb = (const uint32_t*)&r[1];
        const uint32_t* rc = (const uint32_t*)&r[2];
        const uint32_t* rd = (const uint32_t*)&r[3];
        uint4 o;
        uint32_t* op = (uint32_t*)&o;
#pragma unroll
        for (int j = 0; j < 4; j++) {
            float2 fa = __half22float2(*(const __half2*)&ra[j]);
            float2 fb = __half22float2(*(const __half2*)&rb[j]);
            float2 fc = __half22float2(*(const __half2*)&rc[j]);
            float2 fd = __half22float2(*(const __half2*)&rd[j]);
            float vx = wtv.x * fa.x + wtv.y * fb.x + wtv.z * fc.x + wtv.w * fd.x;
            float vy = wtv.x * fa.y + wtv.y * fb.y + wtv.z * fc.y + wtv.w * fd.y;
            op[j] = pack_f16x2(vx, vy);
        }
        *(uint4*)(dst + by) = o;
    };

    // prologue: fill s[0] with kk=0 samples (2 groups per warp)
    {
        uint4 r[4]; float4 wtv; uint32_t by;
        prefetch(ibuf, wbuf, warp, r, wtv, by);
        cvst(r, wtv, by, smp);
        prefetch(ibuf, wbuf, warp + 8, r, wtv, by);
        cvst(r, wtv, by, smp);
    }
    __syncthreads();

    for (int kk = 0; kk < 9; kk++) {
        int p = kk & 1;
        char* nh = smp + (p ^ 1) * 9216;
        const uint4* wf = g_wf + (kk * 8) * 4 * 32;
        const int4* ib1 = ibuf + (kk + 1) * 64;
        const float4* wb1 = wbuf + (kk + 1) * 64;
        bool pf = (kk < 8);
        uint32_t sbh = su32 + p * 9216 + rowpart;

        uint4 ra[2][4]; float4 rw_[2]; uint32_t rby[2];
        if (pf) {
            prefetch(ib1, wb1, warp,     ra[0], rw_[0], rby[0]);
            prefetch(ib1, wb1, warp + 8, ra[1], rw_[1], rby[1]);
        }

        auto do_mma2 = [&](int ks0) {
#pragma unroll
            for (int ks = ks0; ks < ks0 + 2; ks++) {
                uint4 a0 = __ldg(&wf[((warp_m * 2 + 0) * 4 + ks) * 32 + lane]);
                uint4 a1 = __ldg(&wf[((warp_m * 2 + 1) * 4 + ks) * 32 + lane]);
                uint32_t b0[4], b1[4];
                uint32_t hb = sbh + ks * 32;
                ldsm_x4(b0[0], b1[0], b0[1], b1[1], hb);
                ldsm_x4(b0[2], b1[2], b0[3], b1[3], hb + 16 * S_STRIDE);
#pragma unroll
                for (int nt = 0; nt < 4; nt++) {
                    mma_f16(acc[0][nt], (const uint32_t*)&a0, b0[nt], b1[nt]);
                    mma_f16(acc[1][nt], (const uint32_t*)&a1, b0[nt], b1[nt]);
                }
            }
        };

        do_mma2(0);

        if (pf) {
            cvst(ra[0], rw_[0], rby[0], nh);
            cvst(ra[1], rw_[1], rby[1], nh);
        }

        do_mma2(2);

        __syncthreads();
    }

    // epilogue: direct STG from C fragments
    float* ob = out + ((size_t)b * COUT) * NPIX + h * WW + w0;
#pragma unroll
    for (int mt = 0; mt < 2; mt++) {
        int o = warp_m * 32 + mt * 16 + g;
#pragma unroll
        for (int nt = 0; nt < 4; nt++) {
            int px = warp_n * 32 + nt * 8 + 2 * t;
            float* p0 = ob + (size_t)o * NPIX + px;
            *(float2*)p0 = make_float2(acc[mt][nt][0], acc[mt][nt][1]);
            float* p1 = p0 + 8 * (size_t)NPIX;
            *(float2*)p1 = make_float2(acc[mt][nt][2], acc[mt][nt][3]);
        }
    }
}

// ---------------------------------------------------------------------------
extern "C" void kernel_launch(void* const* d_in, const int* in_sizes, int n_in,
                              void* d_out, int out_size) {
    const float* x     = (const float*)d_in[0];
    const float* pre_w = (const float*)d_in[1];
    const float* pre_b = (const float*)d_in[2];
    const float* off_w = (const float*)d_in[3];
    const float* off_b = (const float*)d_in[4];
    const float* mod_w = (const float*)d_in[5];
    const float* mod_b = (const float*)d_in[6];
    const float* reg_w = (const float*)d_in[7];
    float* out = (float*)d_out;

    cudaFuncSetAttribute(k2_offmask, cudaFuncAttributeMaxDynamicSharedMemorySize, K2_SMEM_BYTES);
    cudaFuncSetAttribute(k3_main, cudaFuncAttributeMaxDynamicSharedMemorySize, K3_SMEM_BYTES);

    k0_wt<<<36, 256>>>(reg_w, off_w, mod_w);
    k1_pre<<<BB * HH, 128>>>(x, pre_w, pre_b);
    k2_offmask<<<BB * HH, 256, K2_SMEM_BYTES>>>(off_b, mod_b);
    k3_main<<<BB * HH * 2, 256, K3_SMEM_BYTES>>>(out);
}

// round 12
// speedup vs baseline: 1.7568x; 1.0162x over previous
#include <cuda_runtime.h>
#include <cuda_fp16.h>
#include <math.h>
#include <stdint.h>

#define BB    8
#define CIN   64
#define HH    128
#define WW    128
#define COUT  128
#define NPIX  (HH*WW)           // 16384
#define KTOT  (9*CIN)           // 576

// Scratch (__device__ globals; no allocation)
__device__ __half g_x2h[BB*NPIX*CIN];         // NHWC fp16: [b][h][w][c]
__device__ float g_offm[BB*NPIX*32];          // per-pixel [32]: 0..17 off, 18..26 mask
__device__ uint4 g_wf [9*8*4*32];             // k3 A frags fp16: [kk][mtile8][ks4][lane32]
__device__ uint4 g_w2f[9*2*4*32];             // k2 A frags fp16: [kk][mtile2][ks4][lane32]

__device__ __forceinline__ uint32_t pack_f16x2(float e0, float e1) {
    __half2 h = __floats2half2_rn(e0, e1);
    return *(uint32_t*)&h;
}
__device__ __forceinline__ void mma_f16(float* d, const uint32_t* a, uint32_t b0, uint32_t b1) {
    asm volatile(
        "mma.sync.aligned.m16n8k16.row.col.f32.f16.f16.f32 "
        "{%0,%1,%2,%3}, {%4,%5,%6,%7}, {%8,%9}, {%0,%1,%2,%3};"
        : "+f"(d[0]), "+f"(d[1]), "+f"(d[2]), "+f"(d[3])
        : "r"(a[0]), "r"(a[1]), "r"(a[2]), "r"(a[3]), "r"(b0), "r"(b1));
}
__device__ __forceinline__ uint32_t smem_u32(const void* p) {
    uint32_t a;
    asm("{ .reg .u64 t; cvta.to.shared.u64 t, %1; cvt.u32.u64 %0, t; }" : "=r"(a) : "l"(p));
    return a;
}
__device__ __forceinline__ void ldsm_x4(uint32_t& r0, uint32_t& r1, uint32_t& r2, uint32_t& r3,
                                        uint32_t addr) {
    asm volatile("ldmatrix.sync.aligned.m8n8.x4.shared.b16 {%0,%1,%2,%3}, [%4];"
                 : "=r"(r0), "=r"(r1), "=r"(r2), "=r"(r3) : "r"(addr));
}

// ---------------------------------------------------------------------------
// K0: weight prep — fp16 mma A fragments for k3 and k2.
// ---------------------------------------------------------------------------
__global__ void k0_wt(const float* __restrict__ rw,
                      const float* __restrict__ off_w,
                      const float* __restrict__ mod_w) {
    int i = blockIdx.x * 256 + threadIdx.x;
    if (i < 9 * 8 * 4 * 32) {
        int kk   = i >> 10;
        int rem  = i & 1023;
        int mt   = rem >> 7;
        int rem2 = rem & 127;
        int ks   = rem2 >> 5;
        int lane = rem2 & 31;
        int g = lane >> 2, t = lane & 3;
        int o0 = mt * 16 + g, o1 = o0 + 8;
        int c0 = ks * 16 + 2 * t, c1 = c0 + 8;

        uint4 f;
        f.x = pack_f16x2(rw[(o0 * 64 + c0) * 9 + kk], rw[(o0 * 64 + c0 + 1) * 9 + kk]);
        f.y = pack_f16x2(rw[(o1 * 64 + c0) * 9 + kk], rw[(o1 * 64 + c0 + 1) * 9 + kk]);
        f.z = pack_f16x2(rw[(o0 * 64 + c1) * 9 + kk], rw[(o0 * 64 + c1 + 1) * 9 + kk]);
        f.w = pack_f16x2(rw[(o1 * 64 + c1) * 9 + kk], rw[(o1 * 64 + c1 + 1) * 9 + kk]);
        g_wf[i] = f;
    }
    if (i < 9 * 2 * 4 * 32) {
        int lane = i & 31;
        int ks = (i >> 5) & 3;
        int mt = (i >> 7) & 1;
        int kk = i >> 8;
        int g = lane >> 2, t = lane & 3;
        int o0 = mt * 16 + g, o1 = o0 + 8;
        int c0 = ks * 16 + 2 * t, c1 = c0 + 8;

        auto w2v = [&](int o, int c) -> float {
            if (o < 18)      return off_w[(o * 64 + c) * 9 + kk];
            else if (o < 27) return mod_w[((o - 18) * 64 + c) * 9 + kk];
            return 0.f;
        };
        uint4 f;
        f.x = pack_f16x2(w2v(o0, c0), w2v(o0, c0 + 1));
        f.y = pack_f16x2(w2v(o1, c0), w2v(o1, c0 + 1));
        f.z = pack_f16x2(w2v(o0, c1), w2v(o0, c1 + 1));
        f.w = pack_f16x2(w2v(o1, c1), w2v(o1, c1 + 1));
        g_w2f[i] = f;
    }
}

// ---------------------------------------------------------------------------
// K1: 1x1 pre-conv, NCHW in -> NHWC fp16 (g_x2h)
// ---------------------------------------------------------------------------
__global__ void __launch_bounds__(128) k1_pre(const float* __restrict__ x,
                                              const float* __restrict__ pre_w,
                                              const float* __restrict__ pre_b) {
    __shared__ float wsm[64 * 64];
    __shared__ float bsm[64];
    int tid = threadIdx.x;
    for (int i = tid; i < 4096; i += 128) {
        int co = i & 63, ci = i >> 6;
        wsm[ci * 64 + co] = pre_w[co * 64 + ci];
    }
    if (tid < 64) bsm[tid] = pre_b[tid];
    __syncthreads();

    int bh = blockIdx.x;
    int b = bh >> 7, h = bh & 127;
    int w = tid;

    const float* xp = x + (size_t)b * 64 * NPIX + h * WW + w;
    float xin[64];
#pragma unroll
    for (int ci = 0; ci < 64; ci++) xin[ci] = xp[(size_t)ci * NPIX];

    size_t pbase = ((size_t)bh * WW + w) * 64;
    const float4* wsm4 = (const float4*)wsm;
    const float4* b4 = (const float4*)bsm;
#pragma unroll
    for (int cog = 0; cog < 16; cog++) {
        float4 acc = b4[cog];
#pragma unroll
        for (int ci = 0; ci < 64; ci++) {
            float4 wv = wsm4[ci * 16 + cog];
            acc.x += xin[ci] * wv.x;
            acc.y += xin[ci] * wv.y;
            acc.z += xin[ci] * wv.z;
            acc.w += xin[ci] * wv.w;
        }
        uint2 v = make_uint2(pack_f16x2(acc.x, acc.y), pack_f16x2(acc.z, acc.w));
        *(uint2*)(g_x2h + pbase + cog * 4) = v;
    }
}

// ---------------------------------------------------------------------------
// K2: offset+mask 3x3 conv via single-pass fp16 HMMA + ldmatrix B-frags.
// ---------------------------------------------------------------------------
extern __shared__ float dyn_smem[];
#define S_STRIDE  144   // bytes per px row (64 fp16 data + pad)

__global__ void __launch_bounds__(256) k2_offmask(const float* __restrict__ off_b,
                                                  const float* __restrict__ mod_b) {
    char* smp = (char*)dyn_smem;

    int tid = threadIdx.x;
    int warp = tid >> 5, lane = tid & 31;
    int g = lane >> 2, t = lane & 3;
    int bx = blockIdx.x;
    int b = bx >> 7, h = bx & 127;
    size_t pixbase = (size_t)bx * 128;

    int warp_m = warp >> 2;     // 0..1
    int warp_n = warp & 3;      // 0..3

    int pair = lane >> 3, rr = lane & 7;
    uint32_t su32 = smem_u32(smp);
    uint32_t rowpart = (uint32_t)((warp_n * 32 + ((pair >> 1) << 3) + rr) * S_STRIDE
                                  + (pair & 1) * 16);

    float acc[4][4];
#pragma unroll
    for (int nt = 0; nt < 4; nt++)
#pragma unroll
        for (int j = 0; j < 4; j++) acc[nt][j] = 0.f;

    for (int kk = 0; kk < 9; kk++) {
        int ky = kk / 3, kx = kk - ky * 3;
        __syncthreads();
        int y = h - 1 + ky;
        bool yok = (unsigned)y < 128u;
        const __half* row = g_x2h + ((size_t)(b * 128 + (yok ? y : 0)) * 128) * 64;
        for (int i = tid; i < 1024; i += 256) {
            int px = i >> 3, cg = i & 7;
            int xg = px - 1 + kx;
            uint4 v = make_uint4(0u, 0u, 0u, 0u);
            if (yok && (unsigned)xg < 128u)
                v = *(const uint4*)(row + xg * 64 + cg * 8);
            *(uint4*)(smp + px * S_STRIDE + cg * 16) = v;
        }
        __syncthreads();

        const uint4* wfh = g_w2f + (kk * 2 + warp_m) * 4 * 32;
#pragma unroll
        for (int ks = 0; ks < 4; ks++) {
            uint4 ah = __ldg(&wfh[ks * 32 + lane]);
            uint32_t b0[4], b1[4];
            uint32_t hb = su32 + rowpart + ks * 32;
            ldsm_x4(b0[0], b1[0], b0[1], b1[1], hb);
            ldsm_x4(b0[2], b1[2], b0[3], b1[3], hb + 16 * S_STRIDE);
#pragma unroll
            for (int nt = 0; nt < 4; nt++)
                mma_f16(acc[nt], (const uint32_t*)&ah, b0[nt], b1[nt]);
        }
    }

    int o0 = warp_m * 16 + g, o1 = o0 + 8;
    auto wr = [&](int o, int px, float v) {
        if (o >= 27) return;
        v += (o < 18) ? __ldg(off_b + o) : __ldg(mod_b + o - 18);
        if (o >= 18) v = 2.0f / (1.0f + expf(-v));
        g_offm[(pixbase + px) * 32 + o] = v;
    };
#pragma unroll
    for (int nt = 0; nt < 4; nt++) {
        int px = warp_n * 32 + nt * 8 + 2 * t;
        wr(o0, px,     acc[nt][0]);
        wr(o0, px + 1, acc[nt][1]);
        wr(o1, px,     acc[nt][2]);
        wr(o1, px + 1, acc[nt][3]);
    }
}
#define K2_SMEM_BYTES 18432

// ---------------------------------------------------------------------------
// K3: deformable sampling + single-pass fp16 HMMA, pipelined.
// Block = QUARTER row (32 px), 256 threads / 8 warps, 3 CTAs/SM.
// Warp tile: 16o x 32px (1 m-tile x 4 n-tiles) -> 16 acc regs.
// smem: s[2] 0..9216 (2 x 4608) | OSM 9216 (4224) | IBUF 13440 (4608) |
//       WBUF 18048 (4608) -> total 22656 B
// ---------------------------------------------------------------------------
#define OSM_OFF   9216
#define IBUF_OFF  13440
#define WBUF_OFF  18048
#define K3_SMEM_BYTES 22656

__global__ void __launch_bounds__(256, 3) k3_main(float* __restrict__ out) {
    char* smp = (char*)dyn_smem;

    int tid = threadIdx.x;
    int warp = tid >> 5, lane = tid & 31;
    int g = lane >> 2, t = lane & 3;
    int bx = blockIdx.x;
    int b = bx >> 9;
    int h = (bx >> 2) & 127;
    int seg = bx & 3;
    int w0 = seg * 32;
    size_t pixbase = (((size_t)(b * 128 + h)) * 128 + w0);

    float* osm = (float*)(smp + OSM_OFF);
    int4* ibuf = (int4*)(smp + IBUF_OFF);
    float4* wbuf = (float4*)(smp + WBUF_OFF);

    for (int i = tid; i < 1024; i += 256) {
        int px = i >> 5, j = i & 31;
        osm[px * 33 + j] = g_offm[(pixbase + px) * 32 + j];
    }
    __syncthreads();

    for (int i = tid; i < 9 * 32; i += 256) {
        int kk = i >> 5, px = i & 31;
        int ky = kk / 3, kx = kk - ky * 3;
        float dy = osm[px * 33 + 2 * kk];
        float dx = osm[px * 33 + 2 * kk + 1];
        float m  = osm[px * 33 + 18 + kk];
        float py  = (float)(h - 1 + ky) + dy;
        float pxf = (float)(w0 + px - 1 + kx) + dx;
        float y0f = floorf(py), x0f = floorf(pxf);
        float wy = py - y0f, wx = pxf - x0f;
        int y0 = (int)y0f, x0 = (int)x0f;
        int y1 = y0 + 1, x1 = x0 + 1;
        float w00 = (1.f - wy) * (1.f - wx) * m;
        float w01 = (1.f - wy) * wx * m;
        float w10 = wy * (1.f - wx) * m;
        float w11 = wy * wx * m;
        if ((unsigned)y0 >= 128u) { w00 = 0.f; w01 = 0.f; }
        if ((unsigned)y1 >= 128u) { w10 = 0.f; w11 = 0.f; }
        if ((unsigned)x0 >= 128u) { w00 = 0.f; w10 = 0.f; }
        if ((unsigned)x1 >= 128u) { w01 = 0.f; w11 = 0.f; }
        int yc0 = min(max(y0, 0), 127), yc1 = min(max(y1, 0), 127);
        int xc0 = min(max(x0, 0), 127), xc1 = min(max(x1, 0), 127);
        ibuf[i] = make_int4((yc0 * 128 + xc0) * 64, (yc0 * 128 + xc1) * 64,
                            (yc1 * 128 + xc0) * 64, (yc1 * 128 + xc1) * 64);
        wbuf[i] = make_float4(w00, w01, w10, w11);
    }
    __syncthreads();

    const __half* bbase = g_x2h + (size_t)b * NPIX * 64;
    int pxs = lane >> 3;     // 0..3
    int c8  = lane & 7;      // 0..7 -> uint4 group within 64-ch pixel

    int pair = lane >> 3, rr = lane & 7;
    uint32_t su32 = smem_u32(smp);
    uint32_t rowpart = (uint32_t)((((pair >> 1) << 3) + rr) * S_STRIDE + (pair & 1) * 16);

    float acc[4][4];
#pragma unroll
    for (int nt = 0; nt < 4; nt++)
#pragma unroll
        for (int j = 0; j < 4; j++) acc[nt][j] = 0.f;

    // gather: warp handles px = warp*4 + pxs (one group per warp per kk)
    auto prefetch = [&](const int4* ib, const float4* wb,
                        uint4* r, float4& wtv, uint32_t& by) {
        int px = warp * 4 + pxs;
        int4 off = ib[px];
        wtv = wb[px];
        r[0] = *(const uint4*)(bbase + off.x + c8 * 8);
        r[1] = *(const uint4*)(bbase + off.y + c8 * 8);
        r[2] = *(const uint4*)(bbase + off.z + c8 * 8);
        r[3] = *(const uint4*)(bbase + off.w + c8 * 8);
        by = (uint32_t)(px * S_STRIDE + c8 * 16);
    };
    auto cvst = [&](const uint4* r, float4 wtv, uint32_t by, char* dst) {
        const uint32_t* ra = (const uint32_t*)&r[0];
        const uint32_t* rb = (const uint32_t*)&r[1];
        const uint32_t* rc = (const uint32_t*)&r[2];
        const uint32_t* rd = (const uint32_t*)&r[3];
        uint4 o;
        uint32_t* op = (uint32_t*)&o;
#pragma unroll
        for (int j = 0; j < 4; j++) {
            float2 fa = __half22float2(*(const __half2*)&ra[j]);
            float2 fb = __half22float2(*(const __half2*)&rb[j]);
            float2 fc = __half22float2(*(const __half2*)&rc[j]);
            float2 fd = __half22float2(*(const __half2*)&rd[j]);
            float vx = wtv.x * fa.x + wtv.y * fb.x + wtv.z * fc.x + wtv.w * fd.x;
            float vy = wtv.x * fa.y + wtv.y * fb.y + wtv.z * fc.y + wtv.w * fd.y;
            op[j] = pack_f16x2(vx, vy);
        }
        *(uint4*)(dst + by) = o;
    };

    // prologue: fill s[0] with kk=0 samples
    {
        uint4 r[4]; float4 wtv; uint32_t by;
        prefetch(ibuf, wbuf, r, wtv, by);
        cvst(r, wtv, by, smp);
    }
    __syncthreads();

    for (int kk = 0; kk < 9; kk++) {
        int p = kk & 1;
        char* nh = smp + (p ^ 1) * 4608;
        const uint4* wf = g_wf + (kk * 8 + warp) * 4 * 32;   // this warp's m-tile
        const int4* ib1 = ibuf + (kk + 1) * 32;
        const float4* wb1 = wbuf + (kk + 1) * 32;
        bool pf = (kk < 8);
        uint32_t sbh = su32 + p * 4608 + rowpart;

        uint4 ra[4]; float4 rw_; uint32_t rby;
        if (pf) prefetch(ib1, wb1, ra, rw_, rby);

        auto do_mma2 = [&](int ks0) {
#pragma unroll
            for (int ks = ks0; ks < ks0 + 2; ks++) {
                uint4 a0 = __ldg(&wf[ks * 32 + lane]);
                uint32_t b0[4], b1[4];
                uint32_t hb = sbh + ks * 32;
                ldsm_x4(b0[0], b1[0], b0[1], b1[1], hb);
                ldsm_x4(b0[2], b1[2], b0[3], b1[3], hb + 16 * S_STRIDE);
#pragma unroll
                for (int nt = 0; nt < 4; nt++)
                    mma_f16(acc[nt], (const uint32_t*)&a0, b0[nt], b1[nt]);
            }
        };

        do_mma2(0);

        if (pf) cvst(ra, rw_, rby, nh);

        do_mma2(2);

        __syncthreads();
    }

    // epilogue: direct STG from C fragments
    float* ob = out + ((size_t)b * COUT) * NPIX + h * WW + w0;
    int o = warp * 16 + g;
#pragma unroll
    for (int nt = 0; nt < 4; nt++) {
        int px = nt * 8 + 2 * t;
        float* p0 = ob + (size_t)o * NPIX + px;
        *(float2*)p0 = make_float2(acc[nt][0], acc[nt][1]);
        float* p1 = p0 + 8 * (size_t)NPIX;
        *(float2*)p1 = make_float2(acc[nt][2], acc[nt][3]);
    }
}

// ---------------------------------------------------------------------------
extern "C" void kernel_launch(void* const* d_in, const int* in_sizes, int n_in,
                              void* d_out, int out_size) {
    const float* x     = (const float*)d_in[0];
    const float* pre_w = (const float*)d_in[1];
    const float* pre_b = (const float*)d_in[2];
    const float* off_w = (const float*)d_in[3];
    const float* off_b = (const float*)d_in[4];
    const float* mod_w = (const float*)d_in[5];
    const float* mod_b = (const float*)d_in[6];
    const float* reg_w = (const float*)d_in[7];
    float* out = (float*)d_out;

    cudaFuncSetAttribute(k2_offmask, cudaFuncAttributeMaxDynamicSharedMemorySize, K2_SMEM_BYTES);
    cudaFuncSetAttribute(k3_main, cudaFuncAttributeMaxDynamicSharedMemorySize, K3_SMEM_BYTES);

    k0_wt<<<36, 256>>>(reg_w, off_w, mod_w);
    k1_pre<<<BB * HH, 128>>>(x, pre_w, pre_b);
    k2_offmask<<<BB * HH, 256, K2_SMEM_BYTES>>>(off_b, mod_b);
    k3_main<<<BB * HH * 4, 256, K3_SMEM_BYTES>>>(out);
}

// round 13
// speedup vs baseline: 2.2610x; 1.2870x over previous
#include <cuda_runtime.h>
#include <cuda_fp16.h>
#include <cuda_bf16.h>
#include <math.h>
#include <stdint.h>

#define BB    8
#define CIN   64
#define HH    128
#define WW    128
#define COUT  128
#define NPIX  (HH*WW)           // 16384
#define KTOT  (9*CIN)           // 576

// Scratch (__device__ globals; no allocation)
__device__ __half g_x2h[BB*NPIX*CIN];         // NHWC fp16: [b][h][w][c]
__device__ float g_offm[BB*NPIX*32];          // per-pixel [32]: 0..17 off, 18..26 mask
__device__ uint4 g_wf [9*8*4*32];             // k3 A frags fp16: [kk][mtile8][ks4][lane32]
__device__ uint4 g_w2f[9*2*4*32];             // k2 A frags fp16: [kk][mtile2][ks4][lane32]
__device__ uint2 g_w1fh[4*8*32];              // k1 B frags bf16 hi: [ks4][nt8][lane32]
__device__ uint2 g_w1fl[4*8*32];              // k1 B frags bf16 lo

__device__ __forceinline__ uint32_t pack_f16x2(float e0, float e1) {
    __half2 h = __floats2half2_rn(e0, e1);
    return *(uint32_t*)&h;
}
__device__ __forceinline__ uint32_t pack_bf16x2(float e0, float e1) {
    uint32_t r;
    asm("cvt.rn.bf16x2.f32 %0, %1, %2;" : "=r"(r) : "f"(e1), "f"(e0));
    return r;
}
__device__ __forceinline__ float bf16_hi(float v) {
    __nv_bfloat16 hb = __float2bfloat16(v);
    return __bfloat162float(hb);
}
__device__ __forceinline__ void mma_f16(float* d, const uint32_t* a, uint32_t b0, uint32_t b1) {
    asm volatile(
        "mma.sync.aligned.m16n8k16.row.col.f32.f16.f16.f32 "
        "{%0,%1,%2,%3}, {%4,%5,%6,%7}, {%8,%9}, {%0,%1,%2,%3};"
        : "+f"(d[0]), "+f"(d[1]), "+f"(d[2]), "+f"(d[3])
        : "r"(a[0]), "r"(a[1]), "r"(a[2]), "r"(a[3]), "r"(b0), "r"(b1));
}
__device__ __forceinline__ void mma_bf16(float* d, const uint32_t* a, uint32_t b0, uint32_t b1) {
    asm volatile(
        "mma.sync.aligned.m16n8k16.row.col.f32.bf16.bf16.f32 "
        "{%0,%1,%2,%3}, {%4,%5,%6,%7}, {%8,%9}, {%0,%1,%2,%3};"
        : "+f"(d[0]), "+f"(d[1]), "+f"(d[2]), "+f"(d[3])
        : "r"(a[0]), "r"(a[1]), "r"(a[2]), "r"(a[3]), "r"(b0), "r"(b1));
}
__device__ __forceinline__ uint32_t smem_u32(const void* p) {
    uint32_t a;
    asm("{ .reg .u64 t; cvta.to.shared.u64 t, %1; cvt.u32.u64 %0, t; }" : "=r"(a) : "l"(p));
    return a;
}
__device__ __forceinline__ void ldsm_x4(uint32_t& r0, uint32_t& r1, uint32_t& r2, uint32_t& r3,
                                        uint32_t addr) {
    asm volatile("ldmatrix.sync.aligned.m8n8.x4.shared.b16 {%0,%1,%2,%3}, [%4];"
                 : "=r"(r0), "=r"(r1), "=r"(r2), "=r"(r3) : "r"(addr));
}
__device__ __forceinline__ void ldsm_x4_t(uint32_t& r0, uint32_t& r1, uint32_t& r2, uint32_t& r3,
                                          uint32_t addr) {
    asm volatile("ldmatrix.sync.aligned.m8n8.x4.trans.shared.b16 {%0,%1,%2,%3}, [%4];"
                 : "=r"(r0), "=r"(r1), "=r"(r2), "=r"(r3) : "r"(addr));
}

// ---------------------------------------------------------------------------
// K0: weight prep — fp16 A frags (k3, k2) + bf16 hi/lo B frags (k1).
// ---------------------------------------------------------------------------
__global__ void k0_wt(const float* __restrict__ rw,
                      const float* __restrict__ off_w,
                      const float* __restrict__ mod_w,
                      const float* __restrict__ pre_w) {
    int i = blockIdx.x * 256 + threadIdx.x;
    if (i < 9 * 8 * 4 * 32) {
        int kk   = i >> 10;
        int rem  = i & 1023;
        int mt   = rem >> 7;
        int rem2 = rem & 127;
        int ks   = rem2 >> 5;
        int lane = rem2 & 31;
        int g = lane >> 2, t = lane & 3;
        int o0 = mt * 16 + g, o1 = o0 + 8;
        int c0 = ks * 16 + 2 * t, c1 = c0 + 8;

        uint4 f;
        f.x = pack_f16x2(rw[(o0 * 64 + c0) * 9 + kk], rw[(o0 * 64 + c0 + 1) * 9 + kk]);
        f.y = pack_f16x2(rw[(o1 * 64 + c0) * 9 + kk], rw[(o1 * 64 + c0 + 1) * 9 + kk]);
        f.z = pack_f16x2(rw[(o0 * 64 + c1) * 9 + kk], rw[(o0 * 64 + c1 + 1) * 9 + kk]);
        f.w = pack_f16x2(rw[(o1 * 64 + c1) * 9 + kk], rw[(o1 * 64 + c1 + 1) * 9 + kk]);
        g_wf[i] = f;
    }
    if (i < 9 * 2 * 4 * 32) {
        int lane = i & 31;
        int ks = (i >> 5) & 3;
        int mt = (i >> 7) & 1;
        int kk = i >> 8;
        int g = lane >> 2, t = lane & 3;
        int o0 = mt * 16 + g, o1 = o0 + 8;
        int c0 = ks * 16 + 2 * t, c1 = c0 + 8;

        auto w2v = [&](int o, int c) -> float {
            if (o < 18)      return off_w[(o * 64 + c) * 9 + kk];
            else if (o < 27) return mod_w[((o - 18) * 64 + c) * 9 + kk];
            return 0.f;
        };
        uint4 f;
        f.x = pack_f16x2(w2v(o0, c0), w2v(o0, c0 + 1));
        f.y = pack_f16x2(w2v(o1, c0), w2v(o1, c0 + 1));
        f.z = pack_f16x2(w2v(o0, c1), w2v(o0, c1 + 1));
        f.w = pack_f16x2(w2v(o1, c1), w2v(o1, c1 + 1));
        g_w2f[i] = f;
    }
    if (i < 4 * 8 * 32) {
        // k1 B-frags: B[k=ci][n=co] = pre_w[co*64 + ci]
        int lane = i & 31;
        int nt = (i >> 5) & 7;
        int ks = i >> 8;
        int g = lane >> 2, t = lane & 3;
        int n = nt * 8 + g;
        int k0 = ks * 16 + 2 * t;
        float w00 = pre_w[n * 64 + k0];
        float w01 = pre_w[n * 64 + k0 + 1];
        float w10 = pre_w[n * 64 + k0 + 8];
        float w11 = pre_w[n * 64 + k0 + 9];
        float h00 = bf16_hi(w00), h01 = bf16_hi(w01);
        float h10 = bf16_hi(w10), h11 = bf16_hi(w11);
        g_w1fh[i] = make_uint2(pack_bf16x2(h00, h01), pack_bf16x2(h10, h11));
        g_w1fl[i] = make_uint2(pack_bf16x2(w00 - h00, w01 - h01),
                               pack_bf16x2(w10 - h10, w11 - h11));
    }
}

// ---------------------------------------------------------------------------
// K1: 1x1 pre-conv via bf16 hi/lo 3-pass HMMA.
// Block = one (b,h) row, 256 threads / 8 warps.
// A = X[128px x 64ci] from smem [ci][px] via ldmatrix.trans (m=px, k=ci)
// B = W[64ci x 64co] pre-packed frags (n=co). C: rows=px, cols=co.
// smem: xs_hi[64][136 fp16] (272B rows) | xs_lo | bias
// ---------------------------------------------------------------------------
extern __shared__ float dyn_smem[];
#define K1_XHI  0
#define K1_XLO  17408
#define K1_BIAS 34816
#define K1_SMEM_BYTES 35072

__global__ void __launch_bounds__(256) k1_pre(const float* __restrict__ x,
                                              const float* __restrict__ pre_b) {
    char* smp = (char*)dyn_smem;
    int tid = threadIdx.x;
    int warp = tid >> 5, lane = tid & 31;
    int g = lane >> 2, t = lane & 3;
    int bx = blockIdx.x;
    int b = bx >> 7, h = bx & 127;

    if (tid < 64) ((float*)(smp + K1_BIAS))[tid] = pre_b[tid];

    // load X rows (coalesced) -> smem [ci][px] bf16 hi/lo
    const float* xb = x + ((size_t)(b * 64) * 128 + h) * 128;
    for (int ci = warp; ci < 64; ci += 8) {
        float4 v = *(const float4*)(xb + (size_t)ci * NPIX + lane * 4);
        float h0 = bf16_hi(v.x), h1 = bf16_hi(v.y);
        float h2 = bf16_hi(v.z), h3 = bf16_hi(v.w);
        *(uint2*)(smp + K1_XHI + ci * 272 + lane * 8) =
            make_uint2(pack_bf16x2(h0, h1), pack_bf16x2(h2, h3));
        *(uint2*)(smp + K1_XLO + ci * 272 + lane * 8) =
            make_uint2(pack_bf16x2(v.x - h0, v.y - h1), pack_bf16x2(v.z - h2, v.w - h3));
    }
    __syncthreads();

    uint32_t su32 = smem_u32(smp);
    int rr = lane & 7;
    // trans-ldsm A addressing: matrix pair -> (k-row half, px col half)
    uint32_t a_off = (uint32_t)(((((lane >> 4) & 1) * 8 + rr) * 272)
                                + warp * 32 + ((lane >> 3) & 1) * 16);

    float acc[8][4];
#pragma unroll
    for (int nt = 0; nt < 8; nt++)
#pragma unroll
        for (int j = 0; j < 4; j++) acc[nt][j] = 0.f;

#pragma unroll
    for (int ks = 0; ks < 4; ks++) {
        uint32_t ahi[4], alo[4];
        ldsm_x4_t(ahi[0], ahi[1], ahi[2], ahi[3], su32 + K1_XHI + ks * 4352 + a_off);
        ldsm_x4_t(alo[0], alo[1], alo[2], alo[3], su32 + K1_XLO + ks * 4352 + a_off);
#pragma unroll
        for (int nt = 0; nt < 8; nt++) {
            uint2 bh = __ldg(&g_w1fh[(ks * 8 + nt) * 32 + lane]);
            uint2 bl = __ldg(&g_w1fl[(ks * 8 + nt) * 32 + lane]);
            mma_bf16(acc[nt], ahi, bh.x, bh.y);
            mma_bf16(acc[nt], ahi, bl.x, bl.y);
            mma_bf16(acc[nt], alo, bh.x, bh.y);
        }
    }

    // epilogue: +bias, fp16 pack, half2 stores to g_x2h[px][co]
    __half* op = g_x2h + ((size_t)(b * 128 + h) * 128) * 64;
    const float* bsm = (const float*)(smp + K1_BIAS);
    int px0 = warp * 16 + g;
#pragma unroll
    for (int nt = 0; nt < 8; nt++) {
        float b0 = bsm[nt * 8 + 2 * t];
        float b1 = bsm[nt * 8 + 2 * t + 1];
        *(uint32_t*)(op + (size_t)px0 * 64 + nt * 8 + 2 * t) =
            pack_f16x2(acc[nt][0] + b0, acc[nt][1] + b1);
        *(uint32_t*)(op + (size_t)(px0 + 8) * 64 + nt * 8 + 2 * t) =
            pack_f16x2(acc[nt][2] + b0, acc[nt][3] + b1);
    }
}

// ---------------------------------------------------------------------------
// K2: offset+mask 3x3 conv via single-pass fp16 HMMA.
// Single 3-row smem window [3][130 slots][64ch] (slot = px+1), loaded ONCE.
// All 9 kernel positions read shifted ldmatrix windows. 1 sync total.
// ---------------------------------------------------------------------------
#define K2_ROW 18720   // 130 * 144
#define K2_SMEM_BYTES (3 * K2_ROW)   // 56160
#define S_STRIDE 144

__global__ void __launch_bounds__(256) k2_offmask(const float* __restrict__ off_b,
                                                  const float* __restrict__ mod_b) {
    char* smp = (char*)dyn_smem;

    int tid = threadIdx.x;
    int warp = tid >> 5, lane = tid & 31;
    int g = lane >> 2, t = lane & 3;
    int bx = blockIdx.x;
    int b = bx >> 7, h = bx & 127;
    size_t pixbase = (size_t)bx * 128;

    int warp_m = warp >> 2;     // 0..1
    int warp_n = warp & 3;      // 0..3

    int pair = lane >> 3, rr = lane & 7;
    uint32_t su32 = smem_u32(smp);
    uint32_t rowpart = (uint32_t)((warp_n * 32 + ((pair >> 1) << 3) + rr) * S_STRIDE
                                  + (pair & 1) * 16);

    // load 3 rows (zero-padded) once
    for (int i = tid; i < 3 * 1024; i += 256) {
        int r = i >> 10, rem = i & 1023;
        int px = rem >> 3, cg = rem & 7;
        int y = h - 1 + r;
        uint4 v = make_uint4(0u, 0u, 0u, 0u);
        if ((unsigned)y < 128u)
            v = *(const uint4*)(g_x2h + ((size_t)(b * 128 + y) * 128 + px) * 64 + cg * 8);
        *(uint4*)(smp + r * K2_ROW + (px + 1) * S_STRIDE + cg * 16) = v;
    }
    for (int i = tid; i < 48; i += 256) {
        int r = i >> 4, s = (i >> 3) & 1, cg = i & 7;
        *(uint4*)(smp + r * K2_ROW + (s ? 129 : 0) * S_STRIDE + cg * 16) =
            make_uint4(0u, 0u, 0u, 0u);
    }
    __syncthreads();

    float acc[4][4];
#pragma unroll
    for (int nt = 0; nt < 4; nt++)
#pragma unroll
        for (int j = 0; j < 4; j++) acc[nt][j] = 0.f;

#pragma unroll
    for (int kk = 0; kk < 9; kk++) {
        int ky = kk / 3, kx = kk - ky * 3;
        const uint4* wfh = g_w2f + (kk * 2 + warp_m) * 4 * 32;
        uint32_t base = su32 + ky * K2_ROW + kx * S_STRIDE + rowpart;
#pragma unroll
        for (int ks = 0; ks < 4; ks++) {
            uint4 ah = __ldg(&wfh[ks * 32 + lane]);
            uint32_t b0[4], b1[4];
            uint32_t hb = base + ks * 32;
            ldsm_x4(b0[0], b1[0], b0[1], b1[1], hb);
            ldsm_x4(b0[2], b1[2], b0[3], b1[3], hb + 16 * S_STRIDE);
#pragma unroll
            for (int nt = 0; nt < 4; nt++)
                mma_f16(acc[nt], (const uint32_t*)&ah, b0[nt], b1[nt]);
        }
    }

    int o0 = warp_m * 16 + g, o1 = o0 + 8;
    auto wr = [&](int o, int px, float v) {
        if (o >= 27) return;
        v += (o < 18) ? __ldg(off_b + o) : __ldg(mod_b + o - 18);
        if (o >= 18) v = 2.0f / (1.0f + expf(-v));
        g_offm[(pixbase + px) * 32 + o] = v;
    };
#pragma unroll
    for (int nt = 0; nt < 4; nt++) {
        int px = warp_n * 32 + nt * 8 + 2 * t;
        wr(o0, px,     acc[nt][0]);
        wr(o0, px + 1, acc[nt][1]);
        wr(o1, px,     acc[nt][2]);
        wr(o1, px + 1, acc[nt][3]);
    }
}

// ---------------------------------------------------------------------------
// K3: deformable sampling + single-pass fp16 HMMA, pipelined. (unchanged R12)
// Block = QUARTER row (32 px), 256 threads / 8 warps, 3 CTAs/SM.
// ---------------------------------------------------------------------------
#define OSM_OFF   9216
#define IBUF_OFF  13440
#define WBUF_OFF  18048
#define K3_SMEM_BYTES 22656

__global__ void __launch_bounds__(256, 3) k3_main(float* __restrict__ out) {
    char* smp = (char*)dyn_smem;

    int tid = threadIdx.x;
    int warp = tid >> 5, lane = tid & 31;
    int g = lane >> 2, t = lane & 3;
    int bx = blockIdx.x;
    int b = bx >> 9;
    int h = (bx >> 2) & 127;
    int seg = bx & 3;
    int w0 = seg * 32;
    size_t pixbase = (((size_t)(b * 128 + h)) * 128 + w0);

    float* osm = (float*)(smp + OSM_OFF);
    int4* ibuf = (int4*)(smp + IBUF_OFF);
    float4* wbuf = (float4*)(smp + WBUF_OFF);

    for (int i = tid; i < 1024; i += 256) {
        int px = i >> 5, j = i & 31;
        osm[px * 33 + j] = g_offm[(pixbase + px) * 32 + j];
    }
    __syncthreads();

    for (int i = tid; i < 9 * 32; i += 256) {
        int kk = i >> 5, px = i & 31;
        int ky = kk / 3, kx = kk - ky * 3;
        float dy = osm[px * 33 + 2 * kk];
        float dx = osm[px * 33 + 2 * kk + 1];
        float m  = osm[px * 33 + 18 + kk];
        float py  = (float)(h - 1 + ky) + dy;
        float pxf = (float)(w0 + px - 1 + kx) + dx;
        float y0f = floorf(py), x0f = floorf(pxf);
        float wy = py - y0f, wx = pxf - x0f;
        int y0 = (int)y0f, x0 = (int)x0f;
        int y1 = y0 + 1, x1 = x0 + 1;
        float w00 = (1.f - wy) * (1.f - wx) * m;
        float w01 = (1.f - wy) * wx * m;
        float w10 = wy * (1.f - wx) * m;
        float w11 = wy * wx * m;
        if ((unsigned)y0 >= 128u) { w00 = 0.f; w01 = 0.f; }
        if ((unsigned)y1 >= 128u) { w10 = 0.f; w11 = 0.f; }
        if ((unsigned)x0 >= 128u) { w00 = 0.f; w10 = 0.f; }
        if ((unsigned)x1 >= 128u) { w01 = 0.f; w11 = 0.f; }
        int yc0 = min(max(y0, 0), 127), yc1 = min(max(y1, 0), 127);
        int xc0 = min(max(x0, 0), 127), xc1 = min(max(x1, 0), 127);
        ibuf[i] = make_int4((yc0 * 128 + xc0) * 64, (yc0 * 128 + xc1) * 64,
                            (yc1 * 128 + xc0) * 64, (yc1 * 128 + xc1) * 64);
        wbuf[i] = make_float4(w00, w01, w10, w11);
    }
    __syncthreads();

    const __half* bbase = g_x2h + (size_t)b * NPIX * 64;
    int pxs = lane >> 3;
    int c8  = lane & 7;

    int pair = lane >> 3, rr = lane & 7;
    uint32_t su32 = smem_u32(smp);
    uint32_t rowpart = (uint32_t)((((pair >> 1) << 3) + rr) * S_STRIDE + (pair & 1) * 16);

    float acc[4][4];
#pragma unroll
    for (int nt = 0; nt < 4; nt++)
#pragma unroll
        for (int j = 0; j < 4; j++) acc[nt][j] = 0.f;

    auto prefetch = [&](const int4* ib, const float4* wb,
                        uint4* r, float4& wtv, uint32_t& by) {
        int px = warp * 4 + pxs;
        int4 off = ib[px];
        wtv = wb[px];
        r[0] = *(const uint4*)(bbase + off.x + c8 * 8);
        r[1] = *(const uint4*)(bbase + off.y + c8 * 8);
        r[2] = *(const uint4*)(bbase + off.z + c8 * 8);
        r[3] = *(const uint4*)(bbase + off.w + c8 * 8);
        by = (uint32_t)(px * S_STRIDE + c8 * 16);
    };
    auto cvst = [&](const uint4* r, float4 wtv, uint32_t by, char* dst) {
        const uint32_t* ra = (const uint32_t*)&r[0];
        const uint32_t* rb = (const uint32_t*)&r[1];
        const uint32_t* rc = (const uint32_t*)&r[2];
        const uint32_t* rd = (const uint32_t*)&r[3];
        uint4 o;
        uint32_t* op = (uint32_t*)&o;
#pragma unroll
        for (int j = 0; j < 4; j++) {
            float2 fa = __half22float2(*(const __half2*)&ra[j]);
            float2 fb = __half22float2(*(const __half2*)&rb[j]);
            float2 fc = __half22float2(*(const __half2*)&rc[j]);
            float2 fd = __half22float2(*(const __half2*)&rd[j]);
            float vx = wtv.x * fa.x + wtv.y * fb.x + wtv.z * fc.x + wtv.w * fd.x;
            float vy = wtv.x * fa.y + wtv.y * fb.y + wtv.z * fc.y + wtv.w * fd.y;
            op[j] = pack_f16x2(vx, vy);
        }
        *(uint4*)(dst + by) = o;
    };

    {
        uint4 r[4]; float4 wtv; uint32_t by;
        prefetch(ibuf, wbuf, r, wtv, by);
        cvst(r, wtv, by, smp);
    }
    __syncthreads();

    for (int kk = 0; kk < 9; kk++) {
        int p = kk & 1;
        char* nh = smp + (p ^ 1) * 4608;
        const uint4* wf = g_wf + (kk * 8 + warp) * 4 * 32;
        const int4* ib1 = ibuf + (kk + 1) * 32;
        const float4* wb1 = wbuf + (kk + 1) * 32;
        bool pf = (kk < 8);
        uint32_t sbh = su32 + p * 4608 + rowpart;

        uint4 ra[4]; float4 rw_; uint32_t rby;
        if (pf) prefetch(ib1, wb1, ra, rw_, rby);

        auto do_mma2 = [&](int ks0) {
#pragma unroll
            for (int ks = ks0; ks < ks0 + 2; ks++) {
                uint4 a0 = __ldg(&wf[ks * 32 + lane]);
                uint32_t b0[4], b1[4];
                uint32_t hb = sbh + ks * 32;
                ldsm_x4(b0[0], b1[0], b0[1], b1[1], hb);
                ldsm_x4(b0[2], b1[2], b0[3], b1[3], hb + 16 * S_STRIDE);
#pragma unroll
                for (int nt = 0; nt < 4; nt++)
                    mma_f16(acc[nt], (const uint32_t*)&a0, b0[nt], b1[nt]);
            }
        };

        do_mma2(0);
        if (pf) cvst(ra, rw_, rby, nh);
        do_mma2(2);
        __syncthreads();
    }

    float* ob = out + ((size_t)b * COUT) * NPIX + h * WW + w0;
    int o = warp * 16 + g;
#pragma unroll
    for (int nt = 0; nt < 4; nt++) {
        int px = nt * 8 + 2 * t;
        float* p0 = ob + (size_t)o * NPIX + px;
        *(float2*)p0 = make_float2(acc[nt][0], acc[nt][1]);
        float* p1 = p0 + 8 * (size_t)NPIX;
        *(float2*)p1 = make_float2(acc[nt][2], acc[nt][3]);
    }
}

// ---------------------------------------------------------------------------
extern "C" void kernel_launch(void* const* d_in, const int* in_sizes, int n_in,
                              void* d_out, int out_size) {
    const float* x     = (const float*)d_in[0];
    const float* pre_w = (const float*)d_in[1];
    const float* pre_b = (const float*)d_in[2];
    const float* off_w = (const float*)d_in[3];
    const float* off_b = (const float*)d_in[4];
    const float* mod_w = (const float*)d_in[5];
    const float* mod_b = (const float*)d_in[6];
    const float* reg_w = (const float*)d_in[7];
    float* out = (float*)d_out;

    cudaFuncSetAttribute(k1_pre, cudaFuncAttributeMaxDynamicSharedMemorySize, K1_SMEM_BYTES);
    cudaFuncSetAttribute(k2_offmask, cudaFuncAttributeMaxDynamicSharedMemorySize, K2_SMEM_BYTES);
    cudaFuncSetAttribute(k3_main, cudaFuncAttributeMaxDynamicSharedMemorySize, K3_SMEM_BYTES);

    k0_wt<<<36, 256>>>(reg_w, off_w, mod_w, pre_w);
    k1_pre<<<BB * HH, 256, K1_SMEM_BYTES>>>(x, pre_b);
    k2_offmask<<<BB * HH, 256, K2_SMEM_BYTES>>>(off_b, mod_b);
    k3_main<<<BB * HH * 4, 256, K3_SMEM_BYTES>>>(out);
}

// round 14
// speedup vs baseline: 2.2621x; 1.0005x over previous
#include <cuda_runtime.h>
#include <cuda_fp16.h>
#include <cuda_bf16.h>
#include <math.h>
#include <stdint.h>

#define BB    8
#define CIN   64
#define HH    128
#define WW    128
#define COUT  128
#define NPIX  (HH*WW)           // 16384
#define KTOT  (9*CIN)           // 576

// Scratch (__device__ globals; no allocation)
__device__ __half g_x2h[BB*NPIX*CIN];         // NHWC fp16: [b][h][w][c]
__device__ float g_offm[BB*NPIX*32];          // per-pixel [32]: 0..17 off, 18..26 mask
__device__ uint4 g_wf [9*8*4*32];             // k3 A frags fp16: [kk][mtile8][ks4][lane32]
__device__ uint4 g_w2f[9*2*4*32];             // k2 A frags fp16: [kk][mtile2][ks4][lane32]
__device__ uint2 g_w1fh[4*8*32];              // k1 B frags bf16 hi: [ks4][nt8][lane32]
__device__ uint2 g_w1fl[4*8*32];              // k1 B frags bf16 lo

__device__ __forceinline__ uint32_t pack_f16x2(float e0, float e1) {
    __half2 h = __floats2half2_rn(e0, e1);
    return *(uint32_t*)&h;
}
__device__ __forceinline__ uint32_t pack_bf16x2(float e0, float e1) {
    uint32_t r;
    asm("cvt.rn.bf16x2.f32 %0, %1, %2;" : "=r"(r) : "f"(e1), "f"(e0));
    return r;
}
__device__ __forceinline__ float bf16_hi(float v) {
    __nv_bfloat16 hb = __float2bfloat16(v);
    return __bfloat162float(hb);
}
__device__ __forceinline__ void mma_f16(float* d, const uint32_t* a, uint32_t b0, uint32_t b1) {
    asm volatile(
        "mma.sync.aligned.m16n8k16.row.col.f32.f16.f16.f32 "
        "{%0,%1,%2,%3}, {%4,%5,%6,%7}, {%8,%9}, {%0,%1,%2,%3};"
        : "+f"(d[0]), "+f"(d[1]), "+f"(d[2]), "+f"(d[3])
        : "r"(a[0]), "r"(a[1]), "r"(a[2]), "r"(a[3]), "r"(b0), "r"(b1));
}
__device__ __forceinline__ void mma_bf16(float* d, const uint32_t* a, uint32_t b0, uint32_t b1) {
    asm volatile(
        "mma.sync.aligned.m16n8k16.row.col.f32.bf16.bf16.f32 "
        "{%0,%1,%2,%3}, {%4,%5,%6,%7}, {%8,%9}, {%0,%1,%2,%3};"
        : "+f"(d[0]), "+f"(d[1]), "+f"(d[2]), "+f"(d[3])
        : "r"(a[0]), "r"(a[1]), "r"(a[2]), "r"(a[3]), "r"(b0), "r"(b1));
}
__device__ __forceinline__ uint32_t smem_u32(const void* p) {
    uint32_t a;
    asm("{ .reg .u64 t; cvta.to.shared.u64 t, %1; cvt.u32.u64 %0, t; }" : "=r"(a) : "l"(p));
    return a;
}
__device__ __forceinline__ void ldsm_x4(uint32_t& r0, uint32_t& r1, uint32_t& r2, uint32_t& r3,
                                        uint32_t addr) {
    asm volatile("ldmatrix.sync.aligned.m8n8.x4.shared.b16 {%0,%1,%2,%3}, [%4];"
                 : "=r"(r0), "=r"(r1), "=r"(r2), "=r"(r3) : "r"(addr));
}
__device__ __forceinline__ void ldsm_x4_t(uint32_t& r0, uint32_t& r1, uint32_t& r2, uint32_t& r3,
                                          uint32_t addr) {
    asm volatile("ldmatrix.sync.aligned.m8n8.x4.trans.shared.b16 {%0,%1,%2,%3}, [%4];"
                 : "=r"(r0), "=r"(r1), "=r"(r2), "=r"(r3) : "r"(addr));
}

// ---------------------------------------------------------------------------
// K0: weight prep — fp16 A frags (k3, k2) + bf16 hi/lo B frags (k1).
// ---------------------------------------------------------------------------
__global__ void k0_wt(const float* __restrict__ rw,
                      const float* __restrict__ off_w,
                      const float* __restrict__ mod_w,
                      const float* __restrict__ pre_w) {
    int i = blockIdx.x * 256 + threadIdx.x;
    if (i < 9 * 8 * 4 * 32) {
        int kk   = i >> 10;
        int rem  = i & 1023;
        int mt   = rem >> 7;
        int rem2 = rem & 127;
        int ks   = rem2 >> 5;
        int lane = rem2 & 31;
        int g = lane >> 2, t = lane & 3;
        int o0 = mt * 16 + g, o1 = o0 + 8;
        int c0 = ks * 16 + 2 * t, c1 = c0 + 8;

        uint4 f;
        f.x = pack_f16x2(rw[(o0 * 64 + c0) * 9 + kk], rw[(o0 * 64 + c0 + 1) * 9 + kk]);
        f.y = pack_f16x2(rw[(o1 * 64 + c0) * 9 + kk], rw[(o1 * 64 + c0 + 1) * 9 + kk]);
        f.z = pack_f16x2(rw[(o0 * 64 + c1) * 9 + kk], rw[(o0 * 64 + c1 + 1) * 9 + kk]);
        f.w = pack_f16x2(rw[(o1 * 64 + c1) * 9 + kk], rw[(o1 * 64 + c1 + 1) * 9 + kk]);
        g_wf[i] = f;
    }
    if (i < 9 * 2 * 4 * 32) {
        int lane = i & 31;
        int ks = (i >> 5) & 3;
        int mt = (i >> 7) & 1;
        int kk = i >> 8;
        int g = lane >> 2, t = lane & 3;
        int o0 = mt * 16 + g, o1 = o0 + 8;
        int c0 = ks * 16 + 2 * t, c1 = c0 + 8;

        auto w2v = [&](int o, int c) -> float {
            if (o < 18)      return off_w[(o * 64 + c) * 9 + kk];
            else if (o < 27) return mod_w[((o - 18) * 64 + c) * 9 + kk];
            return 0.f;
        };
        uint4 f;
        f.x = pack_f16x2(w2v(o0, c0), w2v(o0, c0 + 1));
        f.y = pack_f16x2(w2v(o1, c0), w2v(o1, c0 + 1));
        f.z = pack_f16x2(w2v(o0, c1), w2v(o0, c1 + 1));
        f.w = pack_f16x2(w2v(o1, c1), w2v(o1, c1 + 1));
        g_w2f[i] = f;
    }
    if (i < 4 * 8 * 32) {
        int lane = i & 31;
        int nt = (i >> 5) & 7;
        int ks = i >> 8;
        int g = lane >> 2, t = lane & 3;
        int n = nt * 8 + g;
        int k0 = ks * 16 + 2 * t;
        float w00 = pre_w[n * 64 + k0];
        float w01 = pre_w[n * 64 + k0 + 1];
        float w10 = pre_w[n * 64 + k0 + 8];
        float w11 = pre_w[n * 64 + k0 + 9];
        float h00 = bf16_hi(w00), h01 = bf16_hi(w01);
        float h10 = bf16_hi(w10), h11 = bf16_hi(w11);
        g_w1fh[i] = make_uint2(pack_bf16x2(h00, h01), pack_bf16x2(h10, h11));
        g_w1fl[i] = make_uint2(pack_bf16x2(w00 - h00, w01 - h01),
                               pack_bf16x2(w10 - h10, w11 - h11));
    }
}

// ---------------------------------------------------------------------------
// K1: 1x1 pre-conv via bf16 hi/lo 3-pass HMMA. (unchanged R13)
// ---------------------------------------------------------------------------
extern __shared__ float dyn_smem[];
#define K1_XHI  0
#define K1_XLO  17408
#define K1_BIAS 34816
#define K1_SMEM_BYTES 35072

__global__ void __launch_bounds__(256) k1_pre(const float* __restrict__ x,
                                              const float* __restrict__ pre_b) {
    char* smp = (char*)dyn_smem;
    int tid = threadIdx.x;
    int warp = tid >> 5, lane = tid & 31;
    int g = lane >> 2, t = lane & 3;
    int bx = blockIdx.x;
    int b = bx >> 7, h = bx & 127;

    if (tid < 64) ((float*)(smp + K1_BIAS))[tid] = pre_b[tid];

    const float* xb = x + ((size_t)(b * 64) * 128 + h) * 128;
    for (int ci = warp; ci < 64; ci += 8) {
        float4 v = *(const float4*)(xb + (size_t)ci * NPIX + lane * 4);
        float h0 = bf16_hi(v.x), h1 = bf16_hi(v.y);
        float h2 = bf16_hi(v.z), h3 = bf16_hi(v.w);
        *(uint2*)(smp + K1_XHI + ci * 272 + lane * 8) =
            make_uint2(pack_bf16x2(h0, h1), pack_bf16x2(h2, h3));
        *(uint2*)(smp + K1_XLO + ci * 272 + lane * 8) =
            make_uint2(pack_bf16x2(v.x - h0, v.y - h1), pack_bf16x2(v.z - h2, v.w - h3));
    }
    __syncthreads();

    uint32_t su32 = smem_u32(smp);
    int rr = lane & 7;
    uint32_t a_off = (uint32_t)(((((lane >> 4) & 1) * 8 + rr) * 272)
                                + warp * 32 + ((lane >> 3) & 1) * 16);

    float acc[8][4];
#pragma unroll
    for (int nt = 0; nt < 8; nt++)
#pragma unroll
        for (int j = 0; j < 4; j++) acc[nt][j] = 0.f;

#pragma unroll
    for (int ks = 0; ks < 4; ks++) {
        uint32_t ahi[4], alo[4];
        ldsm_x4_t(ahi[0], ahi[1], ahi[2], ahi[3], su32 + K1_XHI + ks * 4352 + a_off);
        ldsm_x4_t(alo[0], alo[1], alo[2], alo[3], su32 + K1_XLO + ks * 4352 + a_off);
#pragma unroll
        for (int nt = 0; nt < 8; nt++) {
            uint2 bh = __ldg(&g_w1fh[(ks * 8 + nt) * 32 + lane]);
            uint2 bl = __ldg(&g_w1fl[(ks * 8 + nt) * 32 + lane]);
            mma_bf16(acc[nt], ahi, bh.x, bh.y);
            mma_bf16(acc[nt], ahi, bl.x, bl.y);
            mma_bf16(acc[nt], alo, bh.x, bh.y);
        }
    }

    __half* op = g_x2h + ((size_t)(b * 128 + h) * 128) * 64;
    const float* bsm = (const float*)(smp + K1_BIAS);
    int px0 = warp * 16 + g;
#pragma unroll
    for (int nt = 0; nt < 8; nt++) {
        float b0 = bsm[nt * 8 + 2 * t];
        float b1 = bsm[nt * 8 + 2 * t + 1];
        *(uint32_t*)(op + (size_t)px0 * 64 + nt * 8 + 2 * t) =
            pack_f16x2(acc[nt][0] + b0, acc[nt][1] + b1);
        *(uint32_t*)(op + (size_t)(px0 + 8) * 64 + nt * 8 + 2 * t) =
            pack_f16x2(acc[nt][2] + b0, acc[nt][3] + b1);
    }
}

// ---------------------------------------------------------------------------
// K2: offset+mask 3x3 conv via single-pass fp16 HMMA. (unchanged R13)
// ---------------------------------------------------------------------------
#define K2_ROW 18720   // 130 * 144
#define K2_SMEM_BYTES (3 * K2_ROW)   // 56160
#define S_STRIDE 144

__global__ void __launch_bounds__(256) k2_offmask(const float* __restrict__ off_b,
                                                  const float* __restrict__ mod_b) {
    char* smp = (char*)dyn_smem;

    int tid = threadIdx.x;
    int warp = tid >> 5, lane = tid & 31;
    int g = lane >> 2, t = lane & 3;
    int bx = blockIdx.x;
    int b = bx >> 7, h = bx & 127;
    size_t pixbase = (size_t)bx * 128;

    int warp_m = warp >> 2;     // 0..1
    int warp_n = warp & 3;      // 0..3

    int pair = lane >> 3, rr = lane & 7;
    uint32_t su32 = smem_u32(smp);
    uint32_t rowpart = (uint32_t)((warp_n * 32 + ((pair >> 1) << 3) + rr) * S_STRIDE
                                  + (pair & 1) * 16);

    for (int i = tid; i < 3 * 1024; i += 256) {
        int r = i >> 10, rem = i & 1023;
        int px = rem >> 3, cg = rem & 7;
        int y = h - 1 + r;
        uint4 v = make_uint4(0u, 0u, 0u, 0u);
        if ((unsigned)y < 128u)
            v = *(const uint4*)(g_x2h + ((size_t)(b * 128 + y) * 128 + px) * 64 + cg * 8);
        *(uint4*)(smp + r * K2_ROW + (px + 1) * S_STRIDE + cg * 16) = v;
    }
    for (int i = tid; i < 48; i += 256) {
        int r = i >> 4, s = (i >> 3) & 1, cg = i & 7;
        *(uint4*)(smp + r * K2_ROW + (s ? 129 : 0) * S_STRIDE + cg * 16) =
            make_uint4(0u, 0u, 0u, 0u);
    }
    __syncthreads();

    float acc[4][4];
#pragma unroll
    for (int nt = 0; nt < 4; nt++)
#pragma unroll
        for (int j = 0; j < 4; j++) acc[nt][j] = 0.f;

#pragma unroll
    for (int kk = 0; kk < 9; kk++) {
        int ky = kk / 3, kx = kk - ky * 3;
        const uint4* wfh = g_w2f + (kk * 2 + warp_m) * 4 * 32;
        uint32_t base = su32 + ky * K2_ROW + kx * S_STRIDE + rowpart;
#pragma unroll
        for (int ks = 0; ks < 4; ks++) {
            uint4 ah = __ldg(&wfh[ks * 32 + lane]);
            uint32_t b0[4], b1[4];
            uint32_t hb = base + ks * 32;
            ldsm_x4(b0[0], b1[0], b0[1], b1[1], hb);
            ldsm_x4(b0[2], b1[2], b0[3], b1[3], hb + 16 * S_STRIDE);
#pragma unroll
            for (int nt = 0; nt < 4; nt++)
                mma_f16(acc[nt], (const uint32_t*)&ah, b0[nt], b1[nt]);
        }
    }

    int o0 = warp_m * 16 + g, o1 = o0 + 8;
    auto wr = [&](int o, int px, float v) {
        if (o >= 27) return;
        v += (o < 18) ? __ldg(off_b + o) : __ldg(mod_b + o - 18);
        if (o >= 18) v = 2.0f / (1.0f + expf(-v));
        g_offm[(pixbase + px) * 32 + o] = v;
    };
#pragma unroll
    for (int nt = 0; nt < 4; nt++) {
        int px = warp_n * 32 + nt * 8 + 2 * t;
        wr(o0, px,     acc[nt][0]);
        wr(o0, px + 1, acc[nt][1]);
        wr(o1, px,     acc[nt][2]);
        wr(o1, px + 1, acc[nt][3]);
    }
}

// ---------------------------------------------------------------------------
// K3: deformable sampling + fp16 HMMA, pipelined.
// Block = QUARTER row (32 px), 128 threads / 4 warps, 5 CTAs/SM.
// Warp tile: 32o x 32px (2 m-tiles x 4 n-tiles) -> 32 acc regs.
// B ldsm redundancy 8x -> 4x, A amortized over 8 MMAs.
// smem: s[2] 0..9216 | OSM 9216 (4224) | IBUF 13440 (4608) | WBUF 18048 (4608)
// ---------------------------------------------------------------------------
#define OSM_OFF   9216
#define IBUF_OFF  13440
#define WBUF_OFF  18048
#define K3_SMEM_BYTES 22656

__global__ void __launch_bounds__(128, 5) k3_main(float* __restrict__ out) {
    char* smp = (char*)dyn_smem;

    int tid = threadIdx.x;
    int warp = tid >> 5, lane = tid & 31;
    int g = lane >> 2, t = lane & 3;
    int bx = blockIdx.x;
    int b = bx >> 9;
    int h = (bx >> 2) & 127;
    int seg = bx & 3;
    int w0 = seg * 32;
    size_t pixbase = (((size_t)(b * 128 + h)) * 128 + w0);

    float* osm = (float*)(smp + OSM_OFF);
    int4* ibuf = (int4*)(smp + IBUF_OFF);
    float4* wbuf = (float4*)(smp + WBUF_OFF);

    for (int i = tid; i < 1024; i += 128) {
        int px = i >> 5, j = i & 31;
        osm[px * 33 + j] = g_offm[(pixbase + px) * 32 + j];
    }
    __syncthreads();

    for (int i = tid; i < 9 * 32; i += 128) {
        int kk = i >> 5, px = i & 31;
        int ky = kk / 3, kx = kk - ky * 3;
        float dy = osm[px * 33 + 2 * kk];
        float dx = osm[px * 33 + 2 * kk + 1];
        float m  = osm[px * 33 + 18 + kk];
        float py  = (float)(h - 1 + ky) + dy;
        float pxf = (float)(w0 + px - 1 + kx) + dx;
        float y0f = floorf(py), x0f = floorf(pxf);
        float wy = py - y0f, wx = pxf - x0f;
        int y0 = (int)y0f, x0 = (int)x0f;
        int y1 = y0 + 1, x1 = x0 + 1;
        float w00 = (1.f - wy) * (1.f - wx) * m;
        float w01 = (1.f - wy) * wx * m;
        float w10 = wy * (1.f - wx) * m;
        float w11 = wy * wx * m;
        if ((unsigned)y0 >= 128u) { w00 = 0.f; w01 = 0.f; }
        if ((unsigned)y1 >= 128u) { w10 = 0.f; w11 = 0.f; }
        if ((unsigned)x0 >= 128u) { w00 = 0.f; w10 = 0.f; }
        if ((unsigned)x1 >= 128u) { w01 = 0.f; w11 = 0.f; }
        int yc0 = min(max(y0, 0), 127), yc1 = min(max(y1, 0), 127);
        int xc0 = min(max(x0, 0), 127), xc1 = min(max(x1, 0), 127);
        ibuf[i] = make_int4((yc0 * 128 + xc0) * 64, (yc0 * 128 + xc1) * 64,
                            (yc1 * 128 + xc0) * 64, (yc1 * 128 + xc1) * 64);
        wbuf[i] = make_float4(w00, w01, w10, w11);
    }
    __syncthreads();

    const __half* bbase = g_x2h + (size_t)b * NPIX * 64;
    int pxs = lane >> 3;     // 0..3
    int c8  = lane & 7;      // 0..7

    int pair = lane >> 3, rr = lane & 7;
    uint32_t su32 = smem_u32(smp);
    uint32_t rowpart = (uint32_t)((((pair >> 1) << 3) + rr) * S_STRIDE + (pair & 1) * 16);

    float acc[2][4][4];
#pragma unroll
    for (int mt = 0; mt < 2; mt++)
#pragma unroll
        for (int nt = 0; nt < 4; nt++)
#pragma unroll
            for (int j = 0; j < 4; j++) acc[mt][nt][j] = 0.f;

    // gather: group (0..7) covers px = group*4 + pxs; each warp does groups warp, warp+4
    auto prefetch = [&](const int4* ib, const float4* wb, int group,
                        uint4* r, float4& wtv, uint32_t& by) {
        int px = group * 4 + pxs;
        int4 off = ib[px];
        wtv = wb[px];
        r[0] = *(const uint4*)(bbase + off.x + c8 * 8);
        r[1] = *(const uint4*)(bbase + off.y + c8 * 8);
        r[2] = *(const uint4*)(bbase + off.z + c8 * 8);
        r[3] = *(const uint4*)(bbase + off.w + c8 * 8);
        by = (uint32_t)(px * S_STRIDE + c8 * 16);
    };
    auto cvst = [&](const uint4* r, float4 wtv, uint32_t by, char* dst) {
        const uint32_t* ra = (const uint32_t*)&r[0];
        const uint32_t* rb = (const uint32_t*)&r[1];
        const uint32_t* rc = (const uint32_t*)&r[2];
        const uint32_t* rd = (const uint32_t*)&r[3];
        uint4 o;
        uint32_t* op = (uint32_t*)&o;
#pragma unroll
        for (int j = 0; j < 4; j++) {
            float2 fa = __half22float2(*(const __half2*)&ra[j]);
            float2 fb = __half22float2(*(const __half2*)&rb[j]);
            float2 fc = __half22float2(*(const __half2*)&rc[j]);
            float2 fd = __half22float2(*(const __half2*)&rd[j]);
            float vx = wtv.x * fa.x + wtv.y * fb.x + wtv.z * fc.x + wtv.w * fd.x;
            float vy = wtv.x * fa.y + wtv.y * fb.y + wtv.z * fc.y + wtv.w * fd.y;
            op[j] = pack_f16x2(vx, vy);
        }
        *(uint4*)(dst + by) = o;
    };

    // prologue: fill s[0] with kk=0 samples
    {
        uint4 r[4]; float4 wtv; uint32_t by;
        prefetch(ibuf, wbuf, warp, r, wtv, by);
        cvst(r, wtv, by, smp);
        prefetch(ibuf, wbuf, warp + 4, r, wtv, by);
        cvst(r, wtv, by, smp);
    }
    __syncthreads();

    for (int kk = 0; kk < 9; kk++) {
        int p = kk & 1;
        char* nh = smp + (p ^ 1) * 4608;
        const uint4* wf = g_wf + (kk * 8) * 4 * 32;
        const int4* ib1 = ibuf + (kk + 1) * 32;
        const float4* wb1 = wbuf + (kk + 1) * 32;
        bool pf = (kk < 8);
        uint32_t sbh = su32 + p * 4608 + rowpart;

        uint4 ra[2][4]; float4 rw_[2]; uint32_t rby[2];
        if (pf) {
            prefetch(ib1, wb1, warp,     ra[0], rw_[0], rby[0]);
            prefetch(ib1, wb1, warp + 4, ra[1], rw_[1], rby[1]);
        }

        auto do_mma2 = [&](int ks0) {
#pragma unroll
            for (int ks = ks0; ks < ks0 + 2; ks++) {
                uint4 a0 = __ldg(&wf[((warp * 2 + 0) * 4 + ks) * 32 + lane]);
                uint4 a1 = __ldg(&wf[((warp * 2 + 1) * 4 + ks) * 32 + lane]);
                uint32_t b0[4], b1[4];
                uint32_t hb = sbh + ks * 32;
                ldsm_x4(b0[0], b1[0], b0[1], b1[1], hb);
                ldsm_x4(b0[2], b1[2], b0[3], b1[3], hb + 16 * S_STRIDE);
#pragma unroll
                for (int nt = 0; nt < 4; nt++) {
                    mma_f16(acc[0][nt], (const uint32_t*)&a0, b0[nt], b1[nt]);
                    mma_f16(acc[1][nt], (const uint32_t*)&a1, b0[nt], b1[nt]);
                }
            }
        };

        do_mma2(0);

        if (pf) {
            cvst(ra[0], rw_[0], rby[0], nh);
            cvst(ra[1], rw_[1], rby[1], nh);
        }

        do_mma2(2);

        __syncthreads();
    }

    // epilogue: direct STG from C fragments
    float* ob = out + ((size_t)b * COUT) * NPIX + h * WW + w0;
#pragma unroll
    for (int mt = 0; mt < 2; mt++) {
        int o = warp * 32 + mt * 16 + g;
#pragma unroll
        for (int nt = 0; nt < 4; nt++) {
            int px = nt * 8 + 2 * t;
            float* p0 = ob + (size_t)o * NPIX + px;
            *(float2*)p0 = make_float2(acc[mt][nt][0], acc[mt][nt][1]);
            float* p1 = p0 + 8 * (size_t)NPIX;
            *(float2*)p1 = make_float2(acc[mt][nt][2], acc[mt][nt][3]);
        }
    }
}

// ---------------------------------------------------------------------------
extern "C" void kernel_launch(void* const* d_in, const int* in_sizes, int n_in,
                              void* d_out, int out_size) {
    const float* x     = (const float*)d_in[0];
    const float* pre_w = (const float*)d_in[1];
    const float* pre_b = (const float*)d_in[2];
    const float* off_w = (const float*)d_in[3];
    const float* off_b = (const float*)d_in[4];
    const float* mod_w = (const float*)d_in[5];
    const float* mod_b = (const float*)d_in[6];
    const float* reg_w = (const float*)d_in[7];
    float* out = (float*)d_out;

    cudaFuncSetAttribute(k1_pre, cudaFuncAttributeMaxDynamicSharedMemorySize, K1_SMEM_BYTES);
    cudaFuncSetAttribute(k2_offmask, cudaFuncAttributeMaxDynamicSharedMemorySize, K2_SMEM_BYTES);
    cudaFuncSetAttribute(k3_main, cudaFuncAttributeMaxDynamicSharedMemorySize, K3_SMEM_BYTES);

    k0_wt<<<36, 256>>>(reg_w, off_w, mod_w, pre_w);
    k1_pre<<<BB * HH, 256, K1_SMEM_BYTES>>>(x, pre_b);
    k2_offmask<<<BB * HH, 256, K2_SMEM_BYTES>>>(off_b, mod_b);
    k3_main<<<BB * HH * 4, 128, K3_SMEM_BYTES>>>(out);
}

// round 15
// speedup vs baseline: 2.3376x; 1.0334x over previous
#include <cuda_runtime.h>
#include <cuda_fp16.h>
#include <cuda_bf16.h>
#include <math.h>
#include <stdint.h>

#define BB    8
#define CIN   64
#define HH    128
#define WW    128
#define COUT  128
#define NPIX  (HH*WW)           // 16384
#define KTOT  (9*CIN)           // 576

// Scratch (__device__ globals; no allocation)
__device__ __half g_x2h[BB*NPIX*CIN];         // NHWC fp16: [b][h][w][c]
__device__ float g_offm[BB*NPIX*32];          // per-pixel [32]: 0..17 off, 18..26 mask
__device__ uint4 g_wf [9*8*4*32];             // k3 A frags fp16: [kk][mtile8][ks4][lane32]
__device__ uint4 g_w2f[9*2*4*32];             // k2 A frags fp16: [kk][mtile2][ks4][lane32]
__device__ uint2 g_w1fh[4*8*32];              // k1 B frags bf16 hi: [ks4][nt8][lane32]
__device__ uint2 g_w1fl[4*8*32];              // k1 B frags bf16 lo

__device__ __forceinline__ uint32_t pack_f16x2(float e0, float e1) {
    __half2 h = __floats2half2_rn(e0, e1);
    return *(uint32_t*)&h;
}
__device__ __forceinline__ uint32_t pack_bf16x2(float e0, float e1) {
    uint32_t r;
    asm("cvt.rn.bf16x2.f32 %0, %1, %2;" : "=r"(r) : "f"(e1), "f"(e0));
    return r;
}
__device__ __forceinline__ float bf16_hi(float v) {
    __nv_bfloat16 hb = __float2bfloat16(v);
    return __bfloat162float(hb);
}
__device__ __forceinline__ void mma_f16(float* d, const uint32_t* a, uint32_t b0, uint32_t b1) {
    asm volatile(
        "mma.sync.aligned.m16n8k16.row.col.f32.f16.f16.f32 "
        "{%0,%1,%2,%3}, {%4,%5,%6,%7}, {%8,%9}, {%0,%1,%2,%3};"
        : "+f"(d[0]), "+f"(d[1]), "+f"(d[2]), "+f"(d[3])
        : "r"(a[0]), "r"(a[1]), "r"(a[2]), "r"(a[3]), "r"(b0), "r"(b1));
}
__device__ __forceinline__ void mma_bf16(float* d, const uint32_t* a, uint32_t b0, uint32_t b1) {
    asm volatile(
        "mma.sync.aligned.m16n8k16.row.col.f32.bf16.bf16.f32 "
        "{%0,%1,%2,%3}, {%4,%5,%6,%7}, {%8,%9}, {%0,%1,%2,%3};"
        : "+f"(d[0]), "+f"(d[1]), "+f"(d[2]), "+f"(d[3])
        : "r"(a[0]), "r"(a[1]), "r"(a[2]), "r"(a[3]), "r"(b0), "r"(b1));
}
__device__ __forceinline__ uint32_t smem_u32(const void* p) {
    uint32_t a;
    asm("{ .reg .u64 t; cvta.to.shared.u64 t, %1; cvt.u32.u64 %0, t; }" : "=r"(a) : "l"(p));
    return a;
}
__device__ __forceinline__ void ldsm_x4(uint32_t& r0, uint32_t& r1, uint32_t& r2, uint32_t& r3,
                                        uint32_t addr) {
    asm volatile("ldmatrix.sync.aligned.m8n8.x4.shared.b16 {%0,%1,%2,%3}, [%4];"
                 : "=r"(r0), "=r"(r1), "=r"(r2), "=r"(r3) : "r"(addr));
}
__device__ __forceinline__ void ldsm_x4_t(uint32_t& r0, uint32_t& r1, uint32_t& r2, uint32_t& r3,
                                          uint32_t addr) {
    asm volatile("ldmatrix.sync.aligned.m8n8.x4.trans.shared.b16 {%0,%1,%2,%3}, [%4];"
                 : "=r"(r0), "=r"(r1), "=r"(r2), "=r"(r3) : "r"(addr));
}

// ---------------------------------------------------------------------------
// K0: weight prep — fp16 A frags (k3, k2) + bf16 hi/lo B frags (k1).
// ---------------------------------------------------------------------------
__global__ void k0_wt(const float* __restrict__ rw,
                      const float* __restrict__ off_w,
                      const float* __restrict__ mod_w,
                      const float* __restrict__ pre_w) {
    int i = blockIdx.x * 256 + threadIdx.x;
    if (i < 9 * 8 * 4 * 32) {
        int kk   = i >> 10;
        int rem  = i & 1023;
        int mt   = rem >> 7;
        int rem2 = rem & 127;
        int ks   = rem2 >> 5;
        int lane = rem2 & 31;
        int g = lane >> 2, t = lane & 3;
        int o0 = mt * 16 + g, o1 = o0 + 8;
        int c0 = ks * 16 + 2 * t, c1 = c0 + 8;

        uint4 f;
        f.x = pack_f16x2(rw[(o0 * 64 + c0) * 9 + kk], rw[(o0 * 64 + c0 + 1) * 9 + kk]);
        f.y = pack_f16x2(rw[(o1 * 64 + c0) * 9 + kk], rw[(o1 * 64 + c0 + 1) * 9 + kk]);
        f.z = pack_f16x2(rw[(o0 * 64 + c1) * 9 + kk], rw[(o0 * 64 + c1 + 1) * 9 + kk]);
        f.w = pack_f16x2(rw[(o1 * 64 + c1) * 9 + kk], rw[(o1 * 64 + c1 + 1) * 9 + kk]);
        g_wf[i] = f;
    }
    if (i < 9 * 2 * 4 * 32) {
        int lane = i & 31;
        int ks = (i >> 5) & 3;
        int mt = (i >> 7) & 1;
        int kk = i >> 8;
        int g = lane >> 2, t = lane & 3;
        int o0 = mt * 16 + g, o1 = o0 + 8;
        int c0 = ks * 16 + 2 * t, c1 = c0 + 8;

        auto w2v = [&](int o, int c) -> float {
            if (o < 18)      return off_w[(o * 64 + c) * 9 + kk];
            else if (o < 27) return mod_w[((o - 18) * 64 + c) * 9 + kk];
            return 0.f;
        };
        uint4 f;
        f.x = pack_f16x2(w2v(o0, c0), w2v(o0, c0 + 1));
        f.y = pack_f16x2(w2v(o1, c0), w2v(o1, c0 + 1));
        f.z = pack_f16x2(w2v(o0, c1), w2v(o0, c1 + 1));
        f.w = pack_f16x2(w2v(o1, c1), w2v(o1, c1 + 1));
        g_w2f[i] = f;
    }
    if (i < 4 * 8 * 32) {
        int lane = i & 31;
        int nt = (i >> 5) & 7;
        int ks = i >> 8;
        int g = lane >> 2, t = lane & 3;
        int n = nt * 8 + g;
        int k0 = ks * 16 + 2 * t;
        float w00 = pre_w[n * 64 + k0];
        float w01 = pre_w[n * 64 + k0 + 1];
        float w10 = pre_w[n * 64 + k0 + 8];
        float w11 = pre_w[n * 64 + k0 + 9];
        float h00 = bf16_hi(w00), h01 = bf16_hi(w01);
        float h10 = bf16_hi(w10), h11 = bf16_hi(w11);
        g_w1fh[i] = make_uint2(pack_bf16x2(h00, h01), pack_bf16x2(h10, h11));
        g_w1fl[i] = make_uint2(pack_bf16x2(w00 - h00, w01 - h01),
                               pack_bf16x2(w10 - h10, w11 - h11));
    }
}

// ---------------------------------------------------------------------------
// K1: 1x1 pre-conv via bf16 hi/lo 3-pass HMMA. (unchanged R13)
// ---------------------------------------------------------------------------
extern __shared__ float dyn_smem[];
#define K1_XHI  0
#define K1_XLO  17408
#define K1_BIAS 34816
#define K1_SMEM_BYTES 35072

__global__ void __launch_bounds__(256) k1_pre(const float* __restrict__ x,
                                              const float* __restrict__ pre_b) {
    char* smp = (char*)dyn_smem;
    int tid = threadIdx.x;
    int warp = tid >> 5, lane = tid & 31;
    int g = lane >> 2, t = lane & 3;
    int bx = blockIdx.x;
    int b = bx >> 7, h = bx & 127;

    if (tid < 64) ((float*)(smp + K1_BIAS))[tid] = pre_b[tid];

    const float* xb = x + ((size_t)(b * 64) * 128 + h) * 128;
    for (int ci = warp; ci < 64; ci += 8) {
        float4 v = *(const float4*)(xb + (size_t)ci * NPIX + lane * 4);
        float h0 = bf16_hi(v.x), h1 = bf16_hi(v.y);
        float h2 = bf16_hi(v.z), h3 = bf16_hi(v.w);
        *(uint2*)(smp + K1_XHI + ci * 272 + lane * 8) =
            make_uint2(pack_bf16x2(h0, h1), pack_bf16x2(h2, h3));
        *(uint2*)(smp + K1_XLO + ci * 272 + lane * 8) =
            make_uint2(pack_bf16x2(v.x - h0, v.y - h1), pack_bf16x2(v.z - h2, v.w - h3));
    }
    __syncthreads();

    uint32_t su32 = smem_u32(smp);
    int rr = lane & 7;
    uint32_t a_off = (uint32_t)(((((lane >> 4) & 1) * 8 + rr) * 272)
                                + warp * 32 + ((lane >> 3) & 1) * 16);

    float acc[8][4];
#pragma unroll
    for (int nt = 0; nt < 8; nt++)
#pragma unroll
        for (int j = 0; j < 4; j++) acc[nt][j] = 0.f;

#pragma unroll
    for (int ks = 0; ks < 4; ks++) {
        uint32_t ahi[4], alo[4];
        ldsm_x4_t(ahi[0], ahi[1], ahi[2], ahi[3], su32 + K1_XHI + ks * 4352 + a_off);
        ldsm_x4_t(alo[0], alo[1], alo[2], alo[3], su32 + K1_XLO + ks * 4352 + a_off);
#pragma unroll
        for (int nt = 0; nt < 8; nt++) {
            uint2 bh = __ldg(&g_w1fh[(ks * 8 + nt) * 32 + lane]);
            uint2 bl = __ldg(&g_w1fl[(ks * 8 + nt) * 32 + lane]);
            mma_bf16(acc[nt], ahi, bh.x, bh.y);
            mma_bf16(acc[nt], ahi, bl.x, bl.y);
            mma_bf16(acc[nt], alo, bh.x, bh.y);
        }
    }

    __half* op = g_x2h + ((size_t)(b * 128 + h) * 128) * 64;
    const float* bsm = (const float*)(smp + K1_BIAS);
    int px0 = warp * 16 + g;
#pragma unroll
    for (int nt = 0; nt < 8; nt++) {
        float b0 = bsm[nt * 8 + 2 * t];
        float b1 = bsm[nt * 8 + 2 * t + 1];
        *(uint32_t*)(op + (size_t)px0 * 64 + nt * 8 + 2 * t) =
            pack_f16x2(acc[nt][0] + b0, acc[nt][1] + b1);
        *(uint32_t*)(op + (size_t)(px0 + 8) * 64 + nt * 8 + 2 * t) =
            pack_f16x2(acc[nt][2] + b0, acc[nt][3] + b1);
    }
}

// ---------------------------------------------------------------------------
// K2: offset+mask 3x3 conv via single-pass fp16 HMMA.
// 3-row smem window loaded once; NEW: smem-staged coalesced epilogue.
// ---------------------------------------------------------------------------
#define K2_ROW 18720   // 130 * 144
#define K2_SMEM_BYTES (3 * K2_ROW)   // 56160
#define S_STRIDE 144

__global__ void __launch_bounds__(256) k2_offmask(const float* __restrict__ off_b,
                                                  const float* __restrict__ mod_b) {
    char* smp = (char*)dyn_smem;

    int tid = threadIdx.x;
    int warp = tid >> 5, lane = tid & 31;
    int g = lane >> 2, t = lane & 3;
    int bx = blockIdx.x;
    int b = bx >> 7, h = bx & 127;
    size_t pixbase = (size_t)bx * 128;

    int warp_m = warp >> 2;     // 0..1
    int warp_n = warp & 3;      // 0..3

    int pair = lane >> 3, rr = lane & 7;
    uint32_t su32 = smem_u32(smp);
    uint32_t rowpart = (uint32_t)((warp_n * 32 + ((pair >> 1) << 3) + rr) * S_STRIDE
                                  + (pair & 1) * 16);

    for (int i = tid; i < 3 * 1024; i += 256) {
        int r = i >> 10, rem = i & 1023;
        int px = rem >> 3, cg = rem & 7;
        int y = h - 1 + r;
        uint4 v = make_uint4(0u, 0u, 0u, 0u);
        if ((unsigned)y < 128u)
            v = *(const uint4*)(g_x2h + ((size_t)(b * 128 + y) * 128 + px) * 64 + cg * 8);
        *(uint4*)(smp + r * K2_ROW + (px + 1) * S_STRIDE + cg * 16) = v;
    }
    for (int i = tid; i < 48; i += 256) {
        int r = i >> 4, s = (i >> 3) & 1, cg = i & 7;
        *(uint4*)(smp + r * K2_ROW + (s ? 129 : 0) * S_STRIDE + cg * 16) =
            make_uint4(0u, 0u, 0u, 0u);
    }
    __syncthreads();

    float acc[4][4];
#pragma unroll
    for (int nt = 0; nt < 4; nt++)
#pragma unroll
        for (int j = 0; j < 4; j++) acc[nt][j] = 0.f;

#pragma unroll
    for (int kk = 0; kk < 9; kk++) {
        int ky = kk / 3, kx = kk - ky * 3;
        const uint4* wfh = g_w2f + (kk * 2 + warp_m) * 4 * 32;
        uint32_t base = su32 + ky * K2_ROW + kx * S_STRIDE + rowpart;
#pragma unroll
        for (int ks = 0; ks < 4; ks++) {
            uint4 ah = __ldg(&wfh[ks * 32 + lane]);
            uint32_t b0[4], b1[4];
            uint32_t hb = base + ks * 32;
            ldsm_x4(b0[0], b1[0], b0[1], b1[1], hb);
            ldsm_x4(b0[2], b1[2], b0[3], b1[3], hb + 16 * S_STRIDE);
#pragma unroll
            for (int nt = 0; nt < 4; nt++)
                mma_f16(acc[nt], (const uint32_t*)&ah, b0[nt], b1[nt]);
        }
    }

    // ---- epilogue: stage in smem [128px][36] then coalesced float4 writes ----
    __syncthreads();   // done reading the conv window
    float* tp = (float*)smp;    // 128*36*4 = 18432 B

    // zero unused channels 27..31 (pad 32..35 never copied)
    for (int i = tid; i < 128 * 5; i += 256) {
        int px = i / 5, j = i - px * 5;
        tp[px * 36 + 27 + j] = 0.f;
    }

    int o0 = warp_m * 16 + g, o1 = o0 + 8;
    auto st = [&](int o, int px, float v) {
        if (o >= 27) return;
        v += (o < 18) ? __ldg(off_b + o) : __ldg(mod_b + o - 18);
        if (o >= 18) v = 2.0f / (1.0f + expf(-v));
        tp[px * 36 + o] = v;
    };
#pragma unroll
    for (int nt = 0; nt < 4; nt++) {
        int px = warp_n * 32 + nt * 8 + 2 * t;
        st(o0, px,     acc[nt][0]);
        st(o0, px + 1, acc[nt][1]);
        st(o1, px,     acc[nt][2]);
        st(o1, px + 1, acc[nt][3]);
    }
    __syncthreads();

    for (int i = tid; i < 1024; i += 256) {
        int px = i >> 3, c4 = i & 7;
        float4 v = *(const float4*)(tp + px * 36 + c4 * 4);
        *(float4*)(g_offm + (pixbase + px) * 32 + c4 * 4) = v;
    }
}

// ---------------------------------------------------------------------------
// K3: deformable sampling + single-pass fp16 HMMA, pipelined. (R12 config)
// Block = QUARTER row (32 px), 256 threads / 8 warps, 3 CTAs/SM.
// Warp tile: 16o x 32px (1 m-tile x 4 n-tiles) -> 16 acc regs.
// smem: s[2] 0..9216 (2 x 4608) | OSM 9216 (4224) | IBUF 13440 (4608) |
//       WBUF 18048 (4608) -> total 22656 B
// ---------------------------------------------------------------------------
#define OSM_OFF   9216
#define IBUF_OFF  13440
#define WBUF_OFF  18048
#define K3_SMEM_BYTES 22656

__global__ void __launch_bounds__(256, 3) k3_main(float* __restrict__ out) {
    char* smp = (char*)dyn_smem;

    int tid = threadIdx.x;
    int warp = tid >> 5, lane = tid & 31;
    int g = lane >> 2, t = lane & 3;
    int bx = blockIdx.x;
    int b = bx >> 9;
    int h = (bx >> 2) & 127;
    int seg = bx & 3;
    int w0 = seg * 32;
    size_t pixbase = (((size_t)(b * 128 + h)) * 128 + w0);

    float* osm = (float*)(smp + OSM_OFF);
    int4* ibuf = (int4*)(smp + IBUF_OFF);
    float4* wbuf = (float4*)(smp + WBUF_OFF);

    for (int i = tid; i < 1024; i += 256) {
        int px = i >> 5, j = i & 31;
        osm[px * 33 + j] = g_offm[(pixbase + px) * 32 + j];
    }
    __syncthreads();

    for (int i = tid; i < 9 * 32; i += 256) {
        int kk = i >> 5, px = i & 31;
        int ky = kk / 3, kx = kk - ky * 3;
        float dy = osm[px * 33 + 2 * kk];
        float dx = osm[px * 33 + 2 * kk + 1];
        float m  = osm[px * 33 + 18 + kk];
        float py  = (float)(h - 1 + ky) + dy;
        float pxf = (float)(w0 + px - 1 + kx) + dx;
        float y0f = floorf(py), x0f = floorf(pxf);
        float wy = py - y0f, wx = pxf - x0f;
        int y0 = (int)y0f, x0 = (int)x0f;
        int y1 = y0 + 1, x1 = x0 + 1;
        float w00 = (1.f - wy) * (1.f - wx) * m;
        float w01 = (1.f - wy) * wx * m;
        float w10 = wy * (1.f - wx) * m;
        float w11 = wy * wx * m;
        if ((unsigned)y0 >= 128u) { w00 = 0.f; w01 = 0.f; }
        if ((unsigned)y1 >= 128u) { w10 = 0.f; w11 = 0.f; }
        if ((unsigned)x0 >= 128u) { w00 = 0.f; w10 = 0.f; }
        if ((unsigned)x1 >= 128u) { w01 = 0.f; w11 = 0.f; }
        int yc0 = min(max(y0, 0), 127), yc1 = min(max(y1, 0), 127);
        int xc0 = min(max(x0, 0), 127), xc1 = min(max(x1, 0), 127);
        ibuf[i] = make_int4((yc0 * 128 + xc0) * 64, (yc0 * 128 + xc1) * 64,
                            (yc1 * 128 + xc0) * 64, (yc1 * 128 + xc1) * 64);
        wbuf[i] = make_float4(w00, w01, w10, w11);
    }
    __syncthreads();

    const __half* bbase = g_x2h + (size_t)b * NPIX * 64;
    int pxs = lane >> 3;     // 0..3
    int c8  = lane & 7;      // 0..7 -> uint4 group within 64-ch pixel

    int pair = lane >> 3, rr = lane & 7;
    uint32_t su32 = smem_u32(smp);
    uint32_t rowpart = (uint32_t)((((pair >> 1) << 3) + rr) * S_STRIDE + (pair & 1) * 16);

    float acc[4][4];
#pragma unroll
    for (int nt = 0; nt < 4; nt++)
#pragma unroll
        for (int j = 0; j < 4; j++) acc[nt][j] = 0.f;

    auto prefetch = [&](const int4* ib, const float4* wb,
                        uint4* r, float4& wtv, uint32_t& by) {
        int px = warp * 4 + pxs;
        int4 off = ib[px];
        wtv = wb[px];
        r[0] = *(const uint4*)(bbase + off.x + c8 * 8);
        r[1] = *(const uint4*)(bbase + off.y + c8 * 8);
        r[2] = *(const uint4*)(bbase + off.z + c8 * 8);
        r[3] = *(const uint4*)(bbase + off.w + c8 * 8);
        by = (uint32_t)(px * S_STRIDE + c8 * 16);
    };
    auto cvst = [&](const uint4* r, float4 wtv, uint32_t by, char* dst) {
        const uint32_t* ra = (const uint32_t*)&r[0];
        const uint32_t* rb = (const uint32_t*)&r[1];
        const uint32_t* rc = (const uint32_t*)&r[2];
        const uint32_t* rd = (const uint32_t*)&r[3];
        uint4 o;
        uint32_t* op = (uint32_t*)&o;
#pragma unroll
        for (int j = 0; j < 4; j++) {
            float2 fa = __half22float2(*(const __half2*)&ra[j]);
            float2 fb = __half22float2(*(const __half2*)&rb[j]);
            float2 fc = __half22float2(*(const __half2*)&rc[j]);
            float2 fd = __half22float2(*(const __half2*)&rd[j]);
            float vx = wtv.x * fa.x + wtv.y * fb.x + wtv.z * fc.x + wtv.w * fd.x;
            float vy = wtv.x * fa.y + wtv.y * fb.y + wtv.z * fc.y + wtv.w * fd.y;
            op[j] = pack_f16x2(vx, vy);
        }
        *(uint4*)(dst + by) = o;
    };

    // prologue: fill s[0] with kk=0 samples
    {
        uint4 r[4]; float4 wtv; uint32_t by;
        prefetch(ibuf, wbuf, r, wtv, by);
        cvst(r, wtv, by, smp);
    }
    __syncthreads();

    for (int kk = 0; kk < 9; kk++) {
        int p = kk & 1;
        char* nh = smp + (p ^ 1) * 4608;
        const uint4* wf = g_wf + (kk * 8 + warp) * 4 * 32;   // this warp's m-tile
        const int4* ib1 = ibuf + (kk + 1) * 32;
        const float4* wb1 = wbuf + (kk + 1) * 32;
        bool pf = (kk < 8);
        uint32_t sbh = su32 + p * 4608 + rowpart;

        uint4 ra[4]; float4 rw_; uint32_t rby;
        if (pf) prefetch(ib1, wb1, ra, rw_, rby);

        auto do_mma2 = [&](int ks0) {
#pragma unroll
            for (int ks = ks0; ks < ks0 + 2; ks++) {
                uint4 a0 = __ldg(&wf[ks * 32 + lane]);
                uint32_t b0[4], b1[4];
                uint32_t hb = sbh + ks * 32;
                ldsm_x4(b0[0], b1[0], b0[1], b1[1], hb);
                ldsm_x4(b0[2], b1[2], b0[3], b1[3], hb + 16 * S_STRIDE);
#pragma unroll
                for (int nt = 0; nt < 4; nt++)
                    mma_f16(acc[nt], (const uint32_t*)&a0, b0[nt], b1[nt]);
            }
        };

        do_mma2(0);

        if (pf) cvst(ra, rw_, rby, nh);

        do_mma2(2);

        __syncthreads();
    }

    // epilogue: direct STG from C fragments
    float* ob = out + ((size_t)b * COUT) * NPIX + h * WW + w0;
    int o = warp * 16 + g;
#pragma unroll
    for (int nt = 0; nt < 4; nt++) {
        int px = nt * 8 + 2 * t;
        float* p0 = ob + (size_t)o * NPIX + px;
        *(float2*)p0 = make_float2(acc[nt][0], acc[nt][1]);
        float* p1 = p0 + 8 * (size_t)NPIX;
        *(float2*)p1 = make_float2(acc[nt][2], acc[nt][3]);
    }
}

// ---------------------------------------------------------------------------
extern "C" void kernel_launch(void* const* d_in, const int* in_sizes, int n_in,
                              void* d_out, int out_size) {
    const float* x     = (const float*)d_in[0];
    const float* pre_w = (const float*)d_in[1];
    const float* pre_b = (const float*)d_in[2];
    const float* off_w = (const float*)d_in[3];
    const float* off_b = (const float*)d_in[4];
    const float* mod_w = (const float*)d_in[5];
    const float* mod_b = (const float*)d_in[6];
    const float* reg_w = (const float*)d_in[7];
    float* out = (float*)d_out;

    cudaFuncSetAttribute(k1_pre, cudaFuncAttributeMaxDynamicSharedMemorySize, K1_SMEM_BYTES);
    cudaFuncSetAttribute(k2_offmask, cudaFuncAttributeMaxDynamicSharedMemorySize, K2_SMEM_BYTES);
    cudaFuncSetAttribute(k3_main, cudaFuncAttributeMaxDynamicSharedMemorySize, K3_SMEM_BYTES);

    k0_wt<<<36, 256>>>(reg_w, off_w, mod_w, pre_w);
    k1_pre<<<BB * HH, 256, K1_SMEM_BYTES>>>(x, pre_b);
    k2_offmask<<<BB * HH, 256, K2_SMEM_BYTES>>>(off_b, mod_b);
    k3_main<<<BB * HH * 4, 256, K3_SMEM_BYTES>>>(out);
}

// round 16
// speedup vs baseline: 2.4262x; 1.0379x over previous
#include <cuda_runtime.h>
#include <cuda_fp16.h>
#include <cuda_bf16.h>
#include <math.h>
#include <stdint.h>

#define BB    8
#define CIN   64
#define HH    128
#define WW    128
#define COUT  128
#define NPIX  (HH*WW)           // 16384
#define KTOT  (9*CIN)           // 576

// Scratch (__device__ globals; no allocation)
__device__ __half g_x2h[BB*NPIX*CIN];         // NHWC fp16: [b][h][w][c]
__device__ float g_offm[BB*NPIX*32];          // per-pixel [32]: 0..17 off, 18..26 mask
__device__ uint4 g_wf [9*8*4*32];             // k3 A frags fp16: [kk][mtile8][ks4][lane32]
__device__ uint4 g_w2f[9*2*4*32];             // k2 A frags fp16: [kk][mtile2][ks4][lane32]
__device__ uint2 g_w1fh[4*8*32];              // k1 B frags bf16 hi: [ks4][nt8][lane32]
__device__ uint2 g_w1fl[4*8*32];              // k1 B frags bf16 lo

__device__ __forceinline__ uint32_t pack_f16x2(float e0, float e1) {
    __half2 h = __floats2half2_rn(e0, e1);
    return *(uint32_t*)&h;
}
__device__ __forceinline__ uint32_t pack_bf16x2(float e0, float e1) {
    uint32_t r;
    asm("cvt.rn.bf16x2.f32 %0, %1, %2;" : "=r"(r) : "f"(e1), "f"(e0));
    return r;
}
__device__ __forceinline__ float bf16_hi(float v) {
    __nv_bfloat16 hb = __float2bfloat16(v);
    return __bfloat162float(hb);
}
__device__ __forceinline__ void mma_f16(float* d, const uint32_t* a, uint32_t b0, uint32_t b1) {
    asm volatile(
        "mma.sync.aligned.m16n8k16.row.col.f32.f16.f16.f32 "
        "{%0,%1,%2,%3}, {%4,%5,%6,%7}, {%8,%9}, {%0,%1,%2,%3};"
        : "+f"(d[0]), "+f"(d[1]), "+f"(d[2]), "+f"(d[3])
        : "r"(a[0]), "r"(a[1]), "r"(a[2]), "r"(a[3]), "r"(b0), "r"(b1));
}
__device__ __forceinline__ void mma_bf16(float* d, const uint32_t* a, uint32_t b0, uint32_t b1) {
    asm volatile(
        "mma.sync.aligned.m16n8k16.row.col.f32.bf16.bf16.f32 "
        "{%0,%1,%2,%3}, {%4,%5,%6,%7}, {%8,%9}, {%0,%1,%2,%3};"
        : "+f"(d[0]), "+f"(d[1]), "+f"(d[2]), "+f"(d[3])
        : "r"(a[0]), "r"(a[1]), "r"(a[2]), "r"(a[3]), "r"(b0), "r"(b1));
}
__device__ __forceinline__ uint32_t smem_u32(const void* p) {
    uint32_t a;
    asm("{ .reg .u64 t; cvta.to.shared.u64 t, %1; cvt.u32.u64 %0, t; }" : "=r"(a) : "l"(p));
    return a;
}
__device__ __forceinline__ void ldsm_x4(uint32_t& r0, uint32_t& r1, uint32_t& r2, uint32_t& r3,
                                        uint32_t addr) {
    asm volatile("ldmatrix.sync.aligned.m8n8.x4.shared.b16 {%0,%1,%2,%3}, [%4];"
                 : "=r"(r0), "=r"(r1), "=r"(r2), "=r"(r3) : "r"(addr));
}
__device__ __forceinline__ void ldsm_x4_t(uint32_t& r0, uint32_t& r1, uint32_t& r2, uint32_t& r3,
                                          uint32_t addr) {
    asm volatile("ldmatrix.sync.aligned.m8n8.x4.trans.shared.b16 {%0,%1,%2,%3}, [%4];"
                 : "=r"(r0), "=r"(r1), "=r"(r2), "=r"(r3) : "r"(addr));
}

// ---------------------------------------------------------------------------
// K0: weight prep — fp16 A frags (k3, k2) + bf16 hi/lo B frags (k1).
// ---------------------------------------------------------------------------
__global__ void k0_wt(const float* __restrict__ rw,
                      const float* __restrict__ off_w,
                      const float* __restrict__ mod_w,
                      const float* __restrict__ pre_w) {
    int i = blockIdx.x * 256 + threadIdx.x;
    if (i < 9 * 8 * 4 * 32) {
        int kk   = i >> 10;
        int rem  = i & 1023;
        int mt   = rem >> 7;
        int rem2 = rem & 127;
        int ks   = rem2 >> 5;
        int lane = rem2 & 31;
        int g = lane >> 2, t = lane & 3;
        int o0 = mt * 16 + g, o1 = o0 + 8;
        int c0 = ks * 16 + 2 * t, c1 = c0 + 8;

        uint4 f;
        f.x = pack_f16x2(rw[(o0 * 64 + c0) * 9 + kk], rw[(o0 * 64 + c0 + 1) * 9 + kk]);
        f.y = pack_f16x2(rw[(o1 * 64 + c0) * 9 + kk], rw[(o1 * 64 + c0 + 1) * 9 + kk]);
        f.z = pack_f16x2(rw[(o0 * 64 + c1) * 9 + kk], rw[(o0 * 64 + c1 + 1) * 9 + kk]);
        f.w = pack_f16x2(rw[(o1 * 64 + c1) * 9 + kk], rw[(o1 * 64 + c1 + 1) * 9 + kk]);
        g_wf[i] = f;
    }
    if (i < 9 * 2 * 4 * 32) {
        int lane = i & 31;
        int ks = (i >> 5) & 3;
        int mt = (i >> 7) & 1;
        int kk = i >> 8;
        int g = lane >> 2, t = lane & 3;
        int o0 = mt * 16 + g, o1 = o0 + 8;
        int c0 = ks * 16 + 2 * t, c1 = c0 + 8;

        auto w2v = [&](int o, int c) -> float {
            if (o < 18)      return off_w[(o * 64 + c) * 9 + kk];
            else if (o < 27) return mod_w[((o - 18) * 64 + c) * 9 + kk];
            return 0.f;
        };
        uint4 f;
        f.x = pack_f16x2(w2v(o0, c0), w2v(o0, c0 + 1));
        f.y = pack_f16x2(w2v(o1, c0), w2v(o1, c0 + 1));
        f.z = pack_f16x2(w2v(o0, c1), w2v(o0, c1 + 1));
        f.w = pack_f16x2(w2v(o1, c1), w2v(o1, c1 + 1));
        g_w2f[i] = f;
    }
    if (i < 4 * 8 * 32) {
        int lane = i & 31;
        int nt = (i >> 5) & 7;
        int ks = i >> 8;
        int g = lane >> 2, t = lane & 3;
        int n = nt * 8 + g;
        int k0 = ks * 16 + 2 * t;
        float w00 = pre_w[n * 64 + k0];
        float w01 = pre_w[n * 64 + k0 + 1];
        float w10 = pre_w[n * 64 + k0 + 8];
        float w11 = pre_w[n * 64 + k0 + 9];
        float h00 = bf16_hi(w00), h01 = bf16_hi(w01);
        float h10 = bf16_hi(w10), h11 = bf16_hi(w11);
        g_w1fh[i] = make_uint2(pack_bf16x2(h00, h01), pack_bf16x2(h10, h11));
        g_w1fl[i] = make_uint2(pack_bf16x2(w00 - h00, w01 - h01),
                               pack_bf16x2(w10 - h10, w11 - h11));
    }
}

// ---------------------------------------------------------------------------
// K1: 1x1 pre-conv via bf16 hi/lo 3-pass HMMA. (unchanged)
// ---------------------------------------------------------------------------
extern __shared__ float dyn_smem[];
#define K1_XHI  0
#define K1_XLO  17408
#define K1_BIAS 34816
#define K1_SMEM_BYTES 35072

__global__ void __launch_bounds__(256) k1_pre(const float* __restrict__ x,
                                              const float* __restrict__ pre_b) {
    char* smp = (char*)dyn_smem;
    int tid = threadIdx.x;
    int warp = tid >> 5, lane = tid & 31;
    int g = lane >> 2, t = lane & 3;
    int bx = blockIdx.x;
    int b = bx >> 7, h = bx & 127;

    if (tid < 64) ((float*)(smp + K1_BIAS))[tid] = pre_b[tid];

    const float* xb = x + ((size_t)(b * 64) * 128 + h) * 128;
    for (int ci = warp; ci < 64; ci += 8) {
        float4 v = *(const float4*)(xb + (size_t)ci * NPIX + lane * 4);
        float h0 = bf16_hi(v.x), h1 = bf16_hi(v.y);
        float h2 = bf16_hi(v.z), h3 = bf16_hi(v.w);
        *(uint2*)(smp + K1_XHI + ci * 272 + lane * 8) =
            make_uint2(pack_bf16x2(h0, h1), pack_bf16x2(h2, h3));
        *(uint2*)(smp + K1_XLO + ci * 272 + lane * 8) =
            make_uint2(pack_bf16x2(v.x - h0, v.y - h1), pack_bf16x2(v.z - h2, v.w - h3));
    }
    __syncthreads();

    uint32_t su32 = smem_u32(smp);
    int rr = lane & 7;
    uint32_t a_off = (uint32_t)(((((lane >> 4) & 1) * 8 + rr) * 272)
                                + warp * 32 + ((lane >> 3) & 1) * 16);

    float acc[8][4];
#pragma unroll
    for (int nt = 0; nt < 8; nt++)
#pragma unroll
        for (int j = 0; j < 4; j++) acc[nt][j] = 0.f;

#pragma unroll
    for (int ks = 0; ks < 4; ks++) {
        uint32_t ahi[4], alo[4];
        ldsm_x4_t(ahi[0], ahi[1], ahi[2], ahi[3], su32 + K1_XHI + ks * 4352 + a_off);
        ldsm_x4_t(alo[0], alo[1], alo[2], alo[3], su32 + K1_XLO + ks * 4352 + a_off);
#pragma unroll
        for (int nt = 0; nt < 8; nt++) {
            uint2 bh = __ldg(&g_w1fh[(ks * 8 + nt) * 32 + lane]);
            uint2 bl = __ldg(&g_w1fl[(ks * 8 + nt) * 32 + lane]);
            mma_bf16(acc[nt], ahi, bh.x, bh.y);
            mma_bf16(acc[nt], ahi, bl.x, bl.y);
            mma_bf16(acc[nt], alo, bh.x, bh.y);
        }
    }

    __half* op = g_x2h + ((size_t)(b * 128 + h) * 128) * 64;
    const float* bsm = (const float*)(smp + K1_BIAS);
    int px0 = warp * 16 + g;
#pragma unroll
    for (int nt = 0; nt < 8; nt++) {
        float b0 = bsm[nt * 8 + 2 * t];
        float b1 = bsm[nt * 8 + 2 * t + 1];
        *(uint32_t*)(op + (size_t)px0 * 64 + nt * 8 + 2 * t) =
            pack_f16x2(acc[nt][0] + b0, acc[nt][1] + b1);
        *(uint32_t*)(op + (size_t)(px0 + 8) * 64 + nt * 8 + 2 * t) =
            pack_f16x2(acc[nt][2] + b0, acc[nt][3] + b1);
    }
}

// ---------------------------------------------------------------------------
// K2: offset+mask 3x3 conv via single-pass fp16 HMMA. (unchanged R15)
// ---------------------------------------------------------------------------
#define K2_ROW 18720   // 130 * 144
#define K2_SMEM_BYTES (3 * K2_ROW)   // 56160
#define S_STRIDE 144

__global__ void __launch_bounds__(256) k2_offmask(const float* __restrict__ off_b,
                                                  const float* __restrict__ mod_b) {
    char* smp = (char*)dyn_smem;

    int tid = threadIdx.x;
    int warp = tid >> 5, lane = tid & 31;
    int g = lane >> 2, t = lane & 3;
    int bx = blockIdx.x;
    int b = bx >> 7, h = bx & 127;
    size_t pixbase = (size_t)bx * 128;

    int warp_m = warp >> 2;     // 0..1
    int warp_n = warp & 3;      // 0..3

    int pair = lane >> 3, rr = lane & 7;
    uint32_t su32 = smem_u32(smp);
    uint32_t rowpart = (uint32_t)((warp_n * 32 + ((pair >> 1) << 3) + rr) * S_STRIDE
                                  + (pair & 1) * 16);

    for (int i = tid; i < 3 * 1024; i += 256) {
        int r = i >> 10, rem = i & 1023;
        int px = rem >> 3, cg = rem & 7;
        int y = h - 1 + r;
        uint4 v = make_uint4(0u, 0u, 0u, 0u);
        if ((unsigned)y < 128u)
            v = *(const uint4*)(g_x2h + ((size_t)(b * 128 + y) * 128 + px) * 64 + cg * 8);
        *(uint4*)(smp + r * K2_ROW + (px + 1) * S_STRIDE + cg * 16) = v;
    }
    for (int i = tid; i < 48; i += 256) {
        int r = i >> 4, s = (i >> 3) & 1, cg = i & 7;
        *(uint4*)(smp + r * K2_ROW + (s ? 129 : 0) * S_STRIDE + cg * 16) =
            make_uint4(0u, 0u, 0u, 0u);
    }
    __syncthreads();

    float acc[4][4];
#pragma unroll
    for (int nt = 0; nt < 4; nt++)
#pragma unroll
        for (int j = 0; j < 4; j++) acc[nt][j] = 0.f;

#pragma unroll
    for (int kk = 0; kk < 9; kk++) {
        int ky = kk / 3, kx = kk - ky * 3;
        const uint4* wfh = g_w2f + (kk * 2 + warp_m) * 4 * 32;
        uint32_t base = su32 + ky * K2_ROW + kx * S_STRIDE + rowpart;
#pragma unroll
        for (int ks = 0; ks < 4; ks++) {
            uint4 ah = __ldg(&wfh[ks * 32 + lane]);
            uint32_t b0[4], b1[4];
            uint32_t hb = base + ks * 32;
            ldsm_x4(b0[0], b1[0], b0[1], b1[1], hb);
            ldsm_x4(b0[2], b1[2], b0[3], b1[3], hb + 16 * S_STRIDE);
#pragma unroll
            for (int nt = 0; nt < 4; nt++)
                mma_f16(acc[nt], (const uint32_t*)&ah, b0[nt], b1[nt]);
        }
    }

    // epilogue: stage in smem [128px][36] then coalesced float4 writes
    __syncthreads();
    float* tp = (float*)smp;

    for (int i = tid; i < 128 * 5; i += 256) {
        int px = i / 5, j = i - px * 5;
        tp[px * 36 + 27 + j] = 0.f;
    }

    int o0 = warp_m * 16 + g, o1 = o0 + 8;
    auto st = [&](int o, int px, float v) {
        if (o >= 27) return;
        v += (o < 18) ? __ldg(off_b + o) : __ldg(mod_b + o - 18);
        if (o >= 18) v = 2.0f / (1.0f + expf(-v));
        tp[px * 36 + o] = v;
    };
#pragma unroll
    for (int nt = 0; nt < 4; nt++) {
        int px = warp_n * 32 + nt * 8 + 2 * t;
        st(o0, px,     acc[nt][0]);
        st(o0, px + 1, acc[nt][1]);
        st(o1, px,     acc[nt][2]);
        st(o1, px + 1, acc[nt][3]);
    }
    __syncthreads();

    for (int i = tid; i < 1024; i += 256) {
        int px = i >> 3, c4 = i & 7;
        float4 v = *(const float4*)(tp + px * 36 + c4 * 4);
        *(float4*)(g_offm + (pixbase + px) * 32 + c4 * 4) = v;
    }
}

// ---------------------------------------------------------------------------
// K3: deformable sampling + single-pass fp16 HMMA.
// NON-pipelined gather (inline between mma halves) -> lower reg pressure,
// __launch_bounds__(256,4) -> 4 CTAs/SM, 32 warps. Inter-warp latency hiding.
// Block = QUARTER row (32 px), 256 threads / 8 warps.
// smem: s[2] 0..9216 | OSM 9216 (4224) | IBUF 13440 (4608) | WBUF 18048 (4608)
// ---------------------------------------------------------------------------
#define OSM_OFF   9216
#define IBUF_OFF  13440
#define WBUF_OFF  18048
#define K3_SMEM_BYTES 22656

__global__ void __launch_bounds__(256, 4) k3_main(float* __restrict__ out) {
    char* smp = (char*)dyn_smem;

    int tid = threadIdx.x;
    int warp = tid >> 5, lane = tid & 31;
    int g = lane >> 2, t = lane & 3;
    int bx = blockIdx.x;
    int b = bx >> 9;
    int h = (bx >> 2) & 127;
    int seg = bx & 3;
    int w0 = seg * 32;
    size_t pixbase = (((size_t)(b * 128 + h)) * 128 + w0);

    float* osm = (float*)(smp + OSM_OFF);
    int4* ibuf = (int4*)(smp + IBUF_OFF);
    float4* wbuf = (float4*)(smp + WBUF_OFF);

    for (int i = tid; i < 1024; i += 256) {
        int px = i >> 5, j = i & 31;
        osm[px * 33 + j] = g_offm[(pixbase + px) * 32 + j];
    }
    __syncthreads();

    for (int i = tid; i < 9 * 32; i += 256) {
        int kk = i >> 5, px = i & 31;
        int ky = kk / 3, kx = kk - ky * 3;
        float dy = osm[px * 33 + 2 * kk];
        float dx = osm[px * 33 + 2 * kk + 1];
        float m  = osm[px * 33 + 18 + kk];
        float py  = (float)(h - 1 + ky) + dy;
        float pxf = (float)(w0 + px - 1 + kx) + dx;
        float y0f = floorf(py), x0f = floorf(pxf);
        float wy = py - y0f, wx = pxf - x0f;
        int y0 = (int)y0f, x0 = (int)x0f;
        int y1 = y0 + 1, x1 = x0 + 1;
        float w00 = (1.f - wy) * (1.f - wx) * m;
        float w01 = (1.f - wy) * wx * m;
        float w10 = wy * (1.f - wx) * m;
        float w11 = wy * wx * m;
        if ((unsigned)y0 >= 128u) { w00 = 0.f; w01 = 0.f; }
        if ((unsigned)y1 >= 128u) { w10 = 0.f; w11 = 0.f; }
        if ((unsigned)x0 >= 128u) { w00 = 0.f; w10 = 0.f; }
        if ((unsigned)x1 >= 128u) { w01 = 0.f; w11 = 0.f; }
        int yc0 = min(max(y0, 0), 127), yc1 = min(max(y1, 0), 127);
        int xc0 = min(max(x0, 0), 127), xc1 = min(max(x1, 0), 127);
        ibuf[i] = make_int4((yc0 * 128 + xc0) * 64, (yc0 * 128 + xc1) * 64,
                            (yc1 * 128 + xc0) * 64, (yc1 * 128 + xc1) * 64);
        wbuf[i] = make_float4(w00, w01, w10, w11);
    }
    __syncthreads();

    const __half* bbase = g_x2h + (size_t)b * NPIX * 64;
    int pxs = lane >> 3;     // 0..3
    int c8  = lane & 7;      // 0..7

    int pair = lane >> 3, rr = lane & 7;
    uint32_t su32 = smem_u32(smp);
    uint32_t rowpart = (uint32_t)((((pair >> 1) << 3) + rr) * S_STRIDE + (pair & 1) * 16);

    float acc[4][4];
#pragma unroll
    for (int nt = 0; nt < 4; nt++)
#pragma unroll
        for (int j = 0; j < 4; j++) acc[nt][j] = 0.f;

    // inline gather + convert + STS (transient registers; no cross-phase live range)
    auto gather_cvst = [&](const int4* ib, const float4* wb, char* dst) {
        int px = warp * 4 + pxs;
        int4 off = ib[px];
        float4 wtv = wb[px];
        uint32_t by = (uint32_t)(px * S_STRIDE + c8 * 16);
        uint4 r0 = *(const uint4*)(bbase + off.x + c8 * 8);
        uint4 r1 = *(const uint4*)(bbase + off.y + c8 * 8);
        uint4 r2 = *(const uint4*)(bbase + off.z + c8 * 8);
        uint4 r3 = *(const uint4*)(bbase + off.w + c8 * 8);
        const uint32_t* ra = (const uint32_t*)&r0;
        const uint32_t* rb = (const uint32_t*)&r1;
        const uint32_t* rc = (const uint32_t*)&r2;
        const uint32_t* rd = (const uint32_t*)&r3;
        uint4 o;
        uint32_t* op = (uint32_t*)&o;
#pragma unroll
        for (int j = 0; j < 4; j++) {
            float2 fa = __half22float2(*(const __half2*)&ra[j]);
            float2 fb = __half22float2(*(const __half2*)&rb[j]);
            float2 fc = __half22float2(*(const __half2*)&rc[j]);
            float2 fd = __half22float2(*(const __half2*)&rd[j]);
            float vx = wtv.x * fa.x + wtv.y * fb.x + wtv.z * fc.x + wtv.w * fd.x;
            float vy = wtv.x * fa.y + wtv.y * fb.y + wtv.z * fc.y + wtv.w * fd.y;
            op[j] = pack_f16x2(vx, vy);
        }
        *(uint4*)(dst + by) = o;
    };

    // prologue: fill s[0] with kk=0 samples
    gather_cvst(ibuf, wbuf, smp);
    __syncthreads();

    for (int kk = 0; kk < 9; kk++) {
        int p = kk & 1;
        char* nh = smp + (p ^ 1) * 4608;
        const uint4* wf = g_wf + (kk * 8 + warp) * 4 * 32;   // this warp's m-tile
        bool pf = (kk < 8);
        uint32_t sbh = su32 + p * 4608 + rowpart;

        auto do_mma2 = [&](int ks0) {
#pragma unroll
            for (int ks = ks0; ks < ks0 + 2; ks++) {
                uint4 a0 = __ldg(&wf[ks * 32 + lane]);
                uint32_t b0[4], b1[4];
                uint32_t hb = sbh + ks * 32;
                ldsm_x4(b0[0], b1[0], b0[1], b1[1], hb);
                ldsm_x4(b0[2], b1[2], b0[3], b1[3], hb + 16 * S_STRIDE);
#pragma unroll
                for (int nt = 0; nt < 4; nt++)
                    mma_f16(acc[nt], (const uint32_t*)&a0, b0[nt], b1[nt]);
            }
        };

        do_mma2(0);

        if (pf) gather_cvst(ibuf + (kk + 1) * 32, wbuf + (kk + 1) * 32, nh);

        do_mma2(2);

        __syncthreads();
    }

    // epilogue: direct STG from C fragments
    float* ob = out + ((size_t)b * COUT) * NPIX + h * WW + w0;
    int o = warp * 16 + g;
#pragma unroll
    for (int nt = 0; nt < 4; nt++) {
        int px = nt * 8 + 2 * t;
        float* p0 = ob + (size_t)o * NPIX + px;
        *(float2*)p0 = make_float2(acc[nt][0], acc[nt][1]);
        float* p1 = p0 + 8 * (size_t)NPIX;
        *(float2*)p1 = make_float2(acc[nt][2], acc[nt][3]);
    }
}

// ---------------------------------------------------------------------------
extern "C" void kernel_launch(void* const* d_in, const int* in_sizes, int n_in,
                              void* d_out, int out_size) {
    const float* x     = (const float*)d_in[0];
    const float* pre_w = (const float*)d_in[1];
    const float* pre_b = (const float*)d_in[2];
    const float* off_w = (const float*)d_in[3];
    const float* off_b = (const float*)d_in[4];
    const float* mod_w = (const float*)d_in[5];
    const float* mod_b = (const float*)d_in[6];
    const float* reg_w = (const float*)d_in[7];
    float* out = (float*)d_out;

    cudaFuncSetAttribute(k1_pre, cudaFuncAttributeMaxDynamicSharedMemorySize, K1_SMEM_BYTES);
    cudaFuncSetAttribute(k2_offmask, cudaFuncAttributeMaxDynamicSharedMemorySize, K2_SMEM_BYTES);
    cudaFuncSetAttribute(k3_main, cudaFuncAttributeMaxDynamicSharedMemorySize, K3_SMEM_BYTES);

    k0_wt<<<36, 256>>>(reg_w, off_w, mod_w, pre_w);
    k1_pre<<<BB * HH, 256, K1_SMEM_BYTES>>>(x, pre_b);
    k2_offmask<<<BB * HH, 256, K2_SMEM_BYTES>>>(off_b, mod_b);
    k3_main<<<BB * HH * 4, 256, K3_SMEM_BYTES>>>(out);
}

// round 17
// speedup vs baseline: 2.5685x; 1.0586x over previous
#include <cuda_runtime.h>
#include <cuda_fp16.h>
#include <cuda_bf16.h>
#include <math.h>
#include <stdint.h>

#define BB    8
#define CIN   64
#define HH    128
#define WW    128
#define COUT  128
#define NPIX  (HH*WW)           // 16384
#define KTOT  (9*CIN)           // 576

// Scratch (__device__ globals; no allocation)
__device__ __half g_x2h[BB*NPIX*CIN];         // NHWC fp16: [b][h][w][c]
__device__ float g_offm[BB*NPIX*32];          // per-pixel [32]: 0..17 off, 18..26 mask
__device__ uint4 g_wf [9*8*4*32];             // k3 A frags fp16: [kk][mtile8][ks4][lane32]
__device__ uint4 g_w2f[9*2*4*32];             // k2 A frags fp16: [kk][mtile2][ks4][lane32]
__device__ uint2 g_w1f[4*8*32];               // k1 B frags fp16: [ks4][nt8][lane32]

__device__ __forceinline__ uint32_t pack_f16x2(float e0, float e1) {
    __half2 h = __floats2half2_rn(e0, e1);
    return *(uint32_t*)&h;
}
__device__ __forceinline__ void mma_f16(float* d, const uint32_t* a, uint32_t b0, uint32_t b1) {
    asm volatile(
        "mma.sync.aligned.m16n8k16.row.col.f32.f16.f16.f32 "
        "{%0,%1,%2,%3}, {%4,%5,%6,%7}, {%8,%9}, {%0,%1,%2,%3};"
        : "+f"(d[0]), "+f"(d[1]), "+f"(d[2]), "+f"(d[3])
        : "r"(a[0]), "r"(a[1]), "r"(a[2]), "r"(a[3]), "r"(b0), "r"(b1));
}
__device__ __forceinline__ uint32_t smem_u32(const void* p) {
    uint32_t a;
    asm("{ .reg .u64 t; cvta.to.shared.u64 t, %1; cvt.u32.u64 %0, t; }" : "=r"(a) : "l"(p));
    return a;
}
__device__ __forceinline__ void ldsm_x4(uint32_t& r0, uint32_t& r1, uint32_t& r2, uint32_t& r3,
                                        uint32_t addr) {
    asm volatile("ldmatrix.sync.aligned.m8n8.x4.shared.b16 {%0,%1,%2,%3}, [%4];"
                 : "=r"(r0), "=r"(r1), "=r"(r2), "=r"(r3) : "r"(addr));
}
__device__ __forceinline__ void ldsm_x4_t(uint32_t& r0, uint32_t& r1, uint32_t& r2, uint32_t& r3,
                                          uint32_t addr) {
    asm volatile("ldmatrix.sync.aligned.m8n8.x4.trans.shared.b16 {%0,%1,%2,%3}, [%4];"
                 : "=r"(r0), "=r"(r1), "=r"(r2), "=r"(r3) : "r"(addr));
}

// ---------------------------------------------------------------------------
// K0: weight prep — fp16 A frags (k3, k2) + fp16 B frags (k1).
// ---------------------------------------------------------------------------
__global__ void k0_wt(const float* __restrict__ rw,
                      const float* __restrict__ off_w,
                      const float* __restrict__ mod_w,
                      const float* __restrict__ pre_w) {
    int i = blockIdx.x * 256 + threadIdx.x;
    if (i < 9 * 8 * 4 * 32) {
        int kk   = i >> 10;
        int rem  = i & 1023;
        int mt   = rem >> 7;
        int rem2 = rem & 127;
        int ks   = rem2 >> 5;
        int lane = rem2 & 31;
        int g = lane >> 2, t = lane & 3;
        int o0 = mt * 16 + g, o1 = o0 + 8;
        int c0 = ks * 16 + 2 * t, c1 = c0 + 8;

        uint4 f;
        f.x = pack_f16x2(rw[(o0 * 64 + c0) * 9 + kk], rw[(o0 * 64 + c0 + 1) * 9 + kk]);
        f.y = pack_f16x2(rw[(o1 * 64 + c0) * 9 + kk], rw[(o1 * 64 + c0 + 1) * 9 + kk]);
        f.z = pack_f16x2(rw[(o0 * 64 + c1) * 9 + kk], rw[(o0 * 64 + c1 + 1) * 9 + kk]);
        f.w = pack_f16x2(rw[(o1 * 64 + c1) * 9 + kk], rw[(o1 * 64 + c1 + 1) * 9 + kk]);
        g_wf[i] = f;
    }
    if (i < 9 * 2 * 4 * 32) {
        int lane = i & 31;
        int ks = (i >> 5) & 3;
        int mt = (i >> 7) & 1;
        int kk = i >> 8;
        int g = lane >> 2, t = lane & 3;
        int o0 = mt * 16 + g, o1 = o0 + 8;
        int c0 = ks * 16 + 2 * t, c1 = c0 + 8;

        auto w2v = [&](int o, int c) -> float {
            if (o < 18)      return off_w[(o * 64 + c) * 9 + kk];
            else if (o < 27) return mod_w[((o - 18) * 64 + c) * 9 + kk];
            return 0.f;
        };
        uint4 f;
        f.x = pack_f16x2(w2v(o0, c0), w2v(o0, c0 + 1));
        f.y = pack_f16x2(w2v(o1, c0), w2v(o1, c0 + 1));
        f.z = pack_f16x2(w2v(o0, c1), w2v(o0, c1 + 1));
        f.w = pack_f16x2(w2v(o1, c1), w2v(o1, c1 + 1));
        g_w2f[i] = f;
    }
    if (i < 4 * 8 * 32) {
        int lane = i & 31;
        int nt = (i >> 5) & 7;
        int ks = i >> 8;
        int g = lane >> 2, t = lane & 3;
        int n = nt * 8 + g;
        int k0 = ks * 16 + 2 * t;
        g_w1f[i] = make_uint2(pack_f16x2(pre_w[n * 64 + k0], pre_w[n * 64 + k0 + 1]),
                              pack_f16x2(pre_w[n * 64 + k0 + 8], pre_w[n * 64 + k0 + 9]));
    }
}

// ---------------------------------------------------------------------------
// K1: 1x1 pre-conv via single-pass fp16 HMMA.
// Block = one (b,h) row, 256 threads / 8 warps.
// A = X[128px x 64ci] from smem [ci][px] fp16 via ldmatrix.trans
// B = W[64ci x 64co] pre-packed fp16 frags. C: rows=px, cols=co.
// smem: xs[64][136 fp16] (272B rows) | bias
// ---------------------------------------------------------------------------
extern __shared__ float dyn_smem[];
#define K1_BIAS 17408
#define K1_SMEM_BYTES 17664

__global__ void __launch_bounds__(256) k1_pre(const float* __restrict__ x,
                                              const float* __restrict__ pre_b) {
    char* smp = (char*)dyn_smem;
    int tid = threadIdx.x;
    int warp = tid >> 5, lane = tid & 31;
    int g = lane >> 2, t = lane & 3;
    int bx = blockIdx.x;
    int b = bx >> 7, h = bx & 127;

    if (tid < 64) ((float*)(smp + K1_BIAS))[tid] = pre_b[tid];

    const float* xb = x + ((size_t)(b * 64) * 128 + h) * 128;
    for (int ci = warp; ci < 64; ci += 8) {
        float4 v = *(const float4*)(xb + (size_t)ci * NPIX + lane * 4);
        *(uint2*)(smp + ci * 272 + lane * 8) =
            make_uint2(pack_f16x2(v.x, v.y), pack_f16x2(v.z, v.w));
    }
    __syncthreads();

    uint32_t su32 = smem_u32(smp);
    int rr = lane & 7;
    uint32_t a_off = (uint32_t)(((((lane >> 4) & 1) * 8 + rr) * 272)
                                + warp * 32 + ((lane >> 3) & 1) * 16);

    float acc[8][4];
#pragma unroll
    for (int nt = 0; nt < 8; nt++)
#pragma unroll
        for (int j = 0; j < 4; j++) acc[nt][j] = 0.f;

#pragma unroll
    for (int ks = 0; ks < 4; ks++) {
        uint32_t a[4];
        ldsm_x4_t(a[0], a[1], a[2], a[3], su32 + ks * 4352 + a_off);
#pragma unroll
        for (int nt = 0; nt < 8; nt++) {
            uint2 bf = __ldg(&g_w1f[(ks * 8 + nt) * 32 + lane]);
            mma_f16(acc[nt], a, bf.x, bf.y);
        }
    }

    __half* op = g_x2h + ((size_t)(b * 128 + h) * 128) * 64;
    const float* bsm = (const float*)(smp + K1_BIAS);
    int px0 = warp * 16 + g;
#pragma unroll
    for (int nt = 0; nt < 8; nt++) {
        float b0 = bsm[nt * 8 + 2 * t];
        float b1 = bsm[nt * 8 + 2 * t + 1];
        *(uint32_t*)(op + (size_t)px0 * 64 + nt * 8 + 2 * t) =
            pack_f16x2(acc[nt][0] + b0, acc[nt][1] + b1);
        *(uint32_t*)(op + (size_t)(px0 + 8) * 64 + nt * 8 + 2 * t) =
            pack_f16x2(acc[nt][2] + b0, acc[nt][3] + b1);
    }
}

// ---------------------------------------------------------------------------
// K2: offset+mask 3x3 conv via single-pass fp16 HMMA. (unchanged R15)
// ---------------------------------------------------------------------------
#define K2_ROW 18720   // 130 * 144
#define K2_SMEM_BYTES (3 * K2_ROW)   // 56160
#define S_STRIDE 144

__global__ void __launch_bounds__(256) k2_offmask(const float* __restrict__ off_b,
                                                  const float* __restrict__ mod_b) {
    char* smp = (char*)dyn_smem;

    int tid = threadIdx.x;
    int warp = tid >> 5, lane = tid & 31;
    int g = lane >> 2, t = lane & 3;
    int bx = blockIdx.x;
    int b = bx >> 7, h = bx & 127;
    size_t pixbase = (size_t)bx * 128;

    int warp_m = warp >> 2;     // 0..1
    int warp_n = warp & 3;      // 0..3

    int pair = lane >> 3, rr = lane & 7;
    uint32_t su32 = smem_u32(smp);
    uint32_t rowpart = (uint32_t)((warp_n * 32 + ((pair >> 1) << 3) + rr) * S_STRIDE
                                  + (pair & 1) * 16);

    for (int i = tid; i < 3 * 1024; i += 256) {
        int r = i >> 10, rem = i & 1023;
        int px = rem >> 3, cg = rem & 7;
        int y = h - 1 + r;
        uint4 v = make_uint4(0u, 0u, 0u, 0u);
        if ((unsigned)y < 128u)
            v = *(const uint4*)(g_x2h + ((size_t)(b * 128 + y) * 128 + px) * 64 + cg * 8);
        *(uint4*)(smp + r * K2_ROW + (px + 1) * S_STRIDE + cg * 16) = v;
    }
    for (int i = tid; i < 48; i += 256) {
        int r = i >> 4, s = (i >> 3) & 1, cg = i & 7;
        *(uint4*)(smp + r * K2_ROW + (s ? 129 : 0) * S_STRIDE + cg * 16) =
            make_uint4(0u, 0u, 0u, 0u);
    }
    __syncthreads();

    float acc[4][4];
#pragma unroll
    for (int nt = 0; nt < 4; nt++)
#pragma unroll
        for (int j = 0; j < 4; j++) acc[nt][j] = 0.f;

#pragma unroll
    for (int kk = 0; kk < 9; kk++) {
        int ky = kk / 3, kx = kk - ky * 3;
        const uint4* wfh = g_w2f + (kk * 2 + warp_m) * 4 * 32;
        uint32_t base = su32 + ky * K2_ROW + kx * S_STRIDE + rowpart;
#pragma unroll
        for (int ks = 0; ks < 4; ks++) {
            uint4 ah = __ldg(&wfh[ks * 32 + lane]);
            uint32_t b0[4], b1[4];
            uint32_t hb = base + ks * 32;
            ldsm_x4(b0[0], b1[0], b0[1], b1[1], hb);
            ldsm_x4(b0[2], b1[2], b0[3], b1[3], hb + 16 * S_STRIDE);
#pragma unroll
            for (int nt = 0; nt < 4; nt++)
                mma_f16(acc[nt], (const uint32_t*)&ah, b0[nt], b1[nt]);
        }
    }

    // epilogue: stage in smem [128px][36] then coalesced float4 writes
    __syncthreads();
    float* tp = (float*)smp;

    for (int i = tid; i < 128 * 5; i += 256) {
        int px = i / 5, j = i - px * 5;
        tp[px * 36 + 27 + j] = 0.f;
    }

    int o0 = warp_m * 16 + g, o1 = o0 + 8;
    auto st = [&](int o, int px, float v) {
        if (o >= 27) return;
        v += (o < 18) ? __ldg(off_b + o) : __ldg(mod_b + o - 18);
        if (o >= 18) v = 2.0f / (1.0f + expf(-v));
        tp[px * 36 + o] = v;
    };
#pragma unroll
    for (int nt = 0; nt < 4; nt++) {
        int px = warp_n * 32 + nt * 8 + 2 * t;
        st(o0, px,     acc[nt][0]);
        st(o0, px + 1, acc[nt][1]);
        st(o1, px,     acc[nt][2]);
        st(o1, px + 1, acc[nt][3]);
    }
    __syncthreads();

    for (int i = tid; i < 1024; i += 256) {
        int px = i >> 3, c4 = i & 7;
        float4 v = *(const float4*)(tp + px * 36 + c4 * 4);
        *(float4*)(g_offm + (pixbase + px) * 32 + c4 * 4) = v;
    }
}

// ---------------------------------------------------------------------------
// K3: deformable sampling + single-pass fp16 HMMA.
// Block = QUARTER row (32 px), 128 threads / 4 warps, 6 CTAs/SM (24 warps).
// Warp tile: 32o x 32px (2 m-tiles x 4 n-tiles) -> halved B-frag redundancy.
// Inline gather (2 groups per warp per kk). 1 sync/kk.
// smem: s[2] 0..9216 | OSM 9216 (4224) | IBUF 13440 (4608) | WBUF 18048 (4608)
// ---------------------------------------------------------------------------
#define OSM_OFF   9216
#define IBUF_OFF  13440
#define WBUF_OFF  18048
#define K3_SMEM_BYTES 22656

__global__ void __launch_bounds__(128, 6) k3_main(float* __restrict__ out) {
    char* smp = (char*)dyn_smem;

    int tid = threadIdx.x;
    int warp = tid >> 5, lane = tid & 31;
    int g = lane >> 2, t = lane & 3;
    int bx = blockIdx.x;
    int b = bx >> 9;
    int h = (bx >> 2) & 127;
    int seg = bx & 3;
    int w0 = seg * 32;
    size_t pixbase = (((size_t)(b * 128 + h)) * 128 + w0);

    float* osm = (float*)(smp + OSM_OFF);
    int4* ibuf = (int4*)(smp + IBUF_OFF);
    float4* wbuf = (float4*)(smp + WBUF_OFF);

    for (int i = tid; i < 1024; i += 128) {
        int px = i >> 5, j = i & 31;
        osm[px * 33 + j] = g_offm[(pixbase + px) * 32 + j];
    }
    __syncthreads();

    for (int i = tid; i < 9 * 32; i += 128) {
        int kk = i >> 5, px = i & 31;
        int ky = kk / 3, kx = kk - ky * 3;
        float dy = osm[px * 33 + 2 * kk];
        float dx = osm[px * 33 + 2 * kk + 1];
        float m  = osm[px * 33 + 18 + kk];
        float py  = (float)(h - 1 + ky) + dy;
        float pxf = (float)(w0 + px - 1 + kx) + dx;
        float y0f = floorf(py), x0f = floorf(pxf);
        float wy = py - y0f, wx = pxf - x0f;
        int y0 = (int)y0f, x0 = (int)x0f;
        int y1 = y0 + 1, x1 = x0 + 1;
        float w00 = (1.f - wy) * (1.f - wx) * m;
        float w01 = (1.f - wy) * wx * m;
        float w10 = wy * (1.f - wx) * m;
        float w11 = wy * wx * m;
        if ((unsigned)y0 >= 128u) { w00 = 0.f; w01 = 0.f; }
        if ((unsigned)y1 >= 128u) { w10 = 0.f; w11 = 0.f; }
        if ((unsigned)x0 >= 128u) { w00 = 0.f; w10 = 0.f; }
        if ((unsigned)x1 >= 128u) { w01 = 0.f; w11 = 0.f; }
        int yc0 = min(max(y0, 0), 127), yc1 = min(max(y1, 0), 127);
        int xc0 = min(max(x0, 0), 127), xc1 = min(max(x1, 0), 127);
        ibuf[i] = make_int4((yc0 * 128 + xc0) * 64, (yc0 * 128 + xc1) * 64,
                            (yc1 * 128 + xc0) * 64, (yc1 * 128 + xc1) * 64);
        wbuf[i] = make_float4(w00, w01, w10, w11);
    }
    __syncthreads();

    const __half* bbase = g_x2h + (size_t)b * NPIX * 64;
    int pxs = lane >> 3;     // 0..3
    int c8  = lane & 7;      // 0..7

    int pair = lane >> 3, rr = lane & 7;
    uint32_t su32 = smem_u32(smp);
    uint32_t rowpart = (uint32_t)((((pair >> 1) << 3) + rr) * S_STRIDE + (pair & 1) * 16);

    float acc[2][4][4];
#pragma unroll
    for (int mt = 0; mt < 2; mt++)
#pragma unroll
        for (int nt = 0; nt < 4; nt++)
#pragma unroll
            for (int j = 0; j < 4; j++) acc[mt][nt][j] = 0.f;

    // inline gather + convert + STS (transient registers)
    auto gather_cvst = [&](const int4* ib, const float4* wb, int group, char* dst) {
        int px = group * 4 + pxs;
        int4 off = ib[px];
        float4 wtv = wb[px];
        uint32_t by = (uint32_t)(px * S_STRIDE + c8 * 16);
        uint4 r0 = *(const uint4*)(bbase + off.x + c8 * 8);
        uint4 r1 = *(const uint4*)(bbase + off.y + c8 * 8);
        uint4 r2 = *(const uint4*)(bbase + off.z + c8 * 8);
        uint4 r3 = *(const uint4*)(bbase + off.w + c8 * 8);
        const uint32_t* ra = (const uint32_t*)&r0;
        const uint32_t* rb = (const uint32_t*)&r1;
        const uint32_t* rc = (const uint32_t*)&r2;
        const uint32_t* rd = (const uint32_t*)&r3;
        uint4 o;
        uint32_t* op = (uint32_t*)&o;
#pragma unroll
        for (int j = 0; j < 4; j++) {
            float2 fa = __half22float2(*(const __half2*)&ra[j]);
            float2 fb = __half22float2(*(const __half2*)&rb[j]);
            float2 fc = __half22float2(*(const __half2*)&rc[j]);
            float2 fd = __half22float2(*(const __half2*)&rd[j]);
            float vx = wtv.x * fa.x + wtv.y * fb.x + wtv.z * fc.x + wtv.w * fd.x;
            float vy = wtv.x * fa.y + wtv.y * fb.y + wtv.z * fc.y + wtv.w * fd.y;
            op[j] = pack_f16x2(vx, vy);
        }
        *(uint4*)(dst + by) = o;
    };

    // prologue: fill s[0] with kk=0 samples
    gather_cvst(ibuf, wbuf, warp, smp);
    gather_cvst(ibuf, wbuf, warp + 4, smp);
    __syncthreads();

    for (int kk = 0; kk < 9; kk++) {
        int p = kk & 1;
        char* nh = smp + (p ^ 1) * 4608;
        const uint4* wf = g_wf + (kk * 8) * 4 * 32;
        bool pf = (kk < 8);
        uint32_t sbh = su32 + p * 4608 + rowpart;

        auto do_mma2 = [&](int ks0) {
#pragma unroll
            for (int ks = ks0; ks < ks0 + 2; ks++) {
                uint4 a0 = __ldg(&wf[((warp * 2 + 0) * 4 + ks) * 32 + lane]);
                uint4 a1 = __ldg(&wf[((warp * 2 + 1) * 4 + ks) * 32 + lane]);
                uint32_t b0[4], b1[4];
                uint32_t hb = sbh + ks * 32;
                ldsm_x4(b0[0], b1[0], b0[1], b1[1], hb);
                ldsm_x4(b0[2], b1[2], b0[3], b1[3], hb + 16 * S_STRIDE);
#pragma unroll
                for (int nt = 0; nt < 4; nt++) {
                    mma_f16(acc[0][nt], (const uint32_t*)&a0, b0[nt], b1[nt]);
                    mma_f16(acc[1][nt], (const uint32_t*)&a1, b0[nt], b1[nt]);
                }
            }
        };

        do_mma2(0);

        if (pf) {
            gather_cvst(ibuf + (kk + 1) * 32, wbuf + (kk + 1) * 32, warp,     nh);
            gather_cvst(ibuf + (kk + 1) * 32, wbuf + (kk + 1) * 32, warp + 4, nh);
        }

        do_mma2(2);

        __syncthreads();
    }

    // epilogue: direct STG from C fragments
    float* ob = out + ((size_t)b * COUT) * NPIX + h * WW + w0;
#pragma unroll
    for (int mt = 0; mt < 2; mt++) {
        int o = warp * 32 + mt * 16 + g;
#pragma unroll
        for (int nt = 0; nt < 4; nt++) {
            int px = nt * 8 + 2 * t;
            float* p0 = ob + (size_t)o * NPIX + px;
            *(float2*)p0 = make_float2(acc[mt][nt][0], acc[mt][nt][1]);
            float* p1 = p0 + 8 * (size_t)NPIX;
            *(float2*)p1 = make_float2(acc[mt][nt][2], acc[mt][nt][3]);
        }
    }
}

// ---------------------------------------------------------------------------
extern "C" void kernel_launch(void* const* d_in, const int* in_sizes, int n_in,
                              void* d_out, int out_size) {
    const float* x     = (const float*)d_in[0];
    const float* pre_w = (const float*)d_in[1];
    const float* pre_b = (const float*)d_in[2];
    const float* off_w = (const float*)d_in[3];
    const float* off_b = (const float*)d_in[4];
    const float* mod_w = (const float*)d_in[5];
    const float* mod_b = (const float*)d_in[6];
    const float* reg_w = (const float*)d_in[7];
    float* out = (float*)d_out;

    cudaFuncSetAttribute(k1_pre, cudaFuncAttributeMaxDynamicSharedMemorySize, K1_SMEM_BYTES);
    cudaFuncSetAttribute(k2_offmask, cudaFuncAttributeMaxDynamicSharedMemorySize, K2_SMEM_BYTES);
    cudaFuncSetAttribute(k3_main, cudaFuncAttributeMaxDynamicSharedMemorySize, K3_SMEM_BYTES);

    k0_wt<<<36, 256>>>(reg_w, off_w, mod_w, pre_w);
    k1_pre<<<BB * HH, 256, K1_SMEM_BYTES>>>(x, pre_b);
    k2_offmask<<<BB * HH, 256, K2_SMEM_BYTES>>>(off_b, mod_b);
    k3_main<<<BB * HH * 4, 128, K3_SMEM_BYTES>>>(out);
}